// round 3
// baseline (speedup 1.0000x reference)
#include <cuda_runtime.h>

// Problem constants (fixed-shape problem)
#define B_DIM 128
#define V_DIM 1024
#define I_DIM 512
#define O_DIM 512
#define G_DIM 16

// Tile config: 128x128 block tile, K-step 16, 256 threads, 8x8 per-thread tile
#define BM 128
#define BN 128
#define BK 16
#define TM 8
#define TN 8

// Decoded per-vertex group index (int32), robust to int32/int64 input dtype.
__device__ int g_decoded[V_DIM];

// Decode group_index buffer. Reads ONLY int32 words 0..1023 for the dtype
// test (always in-bounds: buffer has >=1024 elements of >=4 bytes each).
// int64-LE data with values in [0,16) => all odd int32 words of the first
// 1024 are zero and even words are in range. int32 data => odd words are
// random group ids (P[all zero] ~ 16^-512).
__global__ void decode_gidx_kernel(const int* __restrict__ gidx_i32) {
    __shared__ int is_i32;  // nonzero -> treat as int32
    const int v = threadIdx.x;  // 0..1023
    if (v == 0) is_i32 = 0;
    __syncthreads();

    // dtype test over first 1024 int32 words
    {
        const int w = gidx_i32[v];
        if (v & 1) {
            if (w != 0) atomicOr(&is_i32, 1);
        } else {
            if (w < 0 || w >= G_DIM) atomicOr(&is_i32, 1);
        }
    }
    __syncthreads();

    int g;
    if (is_i32) {
        g = gidx_i32[v];                 // int32 layout: element v
    } else {
        g = gidx_i32[2 * v];             // int64-LE layout: low word of element v
    }
    // final clamp (defensive; correctness unaffected for valid inputs)
    if (g < 0) g = 0;
    if (g >= G_DIM) g = G_DIM - 1;
    g_decoded[v] = g;
}

__global__ __launch_bounds__(256, 2) void glinear_sgemm_kernel(
    const float* __restrict__ x,        // [B, V, I]
    const float* __restrict__ weight,   // [G, O, I]
    const float* __restrict__ bias,     // [G, O]
    float* __restrict__ out)            // [B, V, O]
{
    const int v     = blockIdx.z;        // vertex index 0..1023
    const int ntile = blockIdx.x;        // output-column tile 0..3
    const int g     = g_decoded[v];

    // A = x[:, v, :]  : M=B_DIM rows, K=I_DIM, row stride V_DIM*I_DIM
    // W = weight[g, ntile*BN : +BN, :] : N=BN rows, K=I_DIM, row stride I_DIM
    const float* A    = x + (size_t)v * I_DIM;
    const float* W    = weight + (size_t)g * O_DIM * I_DIM + (size_t)ntile * BN * I_DIM;
    const float* bptr = bias + (size_t)g * O_DIM + (size_t)ntile * BN;
    float*       C    = out + (size_t)v * O_DIM + (size_t)ntile * BN;

    const size_t strideA = (size_t)V_DIM * I_DIM;  // x row stride (floats)
    const size_t strideC = (size_t)V_DIM * O_DIM;  // out row stride (floats)

    __shared__ float As[BK][BM];  // transposed A tile: As[k][m]
    __shared__ float Bs[BK][BN];  // transposed W tile: Bs[k][n]

    const int tid  = threadIdx.x;      // 0..255
    const int tcol = tid & 15;         // 16 column-groups of TN=8
    const int trow = tid >> 4;         // 16 row-groups of TM=8

    // Loader mapping: each thread loads 2 float4 per matrix per K-step.
    const int l_m  = tid >> 2;         // 0..63 (row within tile, +64 for second)
    const int l_k4 = (tid & 3) * 4;    // k offset {0,4,8,12}

    float acc[TM][TN];
#pragma unroll
    for (int i = 0; i < TM; i++)
#pragma unroll
        for (int j = 0; j < TN; j++)
            acc[i][j] = 0.0f;

    for (int k0 = 0; k0 < I_DIM; k0 += BK) {
        // --- load A tile (transposed into As[k][m]) ---
#pragma unroll
        for (int half = 0; half < 2; half++) {
            const int m = l_m + half * 64;
            const float4 va = *(const float4*)(A + (size_t)m * strideA + k0 + l_k4);
            As[l_k4 + 0][m] = va.x;
            As[l_k4 + 1][m] = va.y;
            As[l_k4 + 2][m] = va.z;
            As[l_k4 + 3][m] = va.w;
        }
        // --- load W tile (transposed into Bs[k][n]) ---
#pragma unroll
        for (int half = 0; half < 2; half++) {
            const int n = l_m + half * 64;
            const float4 vb = *(const float4*)(W + (size_t)n * I_DIM + k0 + l_k4);
            Bs[l_k4 + 0][n] = vb.x;
            Bs[l_k4 + 1][n] = vb.y;
            Bs[l_k4 + 2][n] = vb.z;
            Bs[l_k4 + 3][n] = vb.w;
        }
        __syncthreads();

        // --- compute 8x8 per-thread outer products over BK ---
#pragma unroll
        for (int k = 0; k < BK; k++) {
            float a_frag[TM], b_frag[TN];
#pragma unroll
            for (int i = 0; i < TM; i++) a_frag[i] = As[k][trow * TM + i];
#pragma unroll
            for (int j = 0; j < TN; j++) b_frag[j] = Bs[k][tcol * TN + j];
#pragma unroll
            for (int i = 0; i < TM; i++)
#pragma unroll
                for (int j = 0; j < TN; j++)
                    acc[i][j] = fmaf(a_frag[i], b_frag[j], acc[i][j]);
        }
        __syncthreads();
    }

    // --- epilogue: add bias, write out ---
    float bfrag[TN];
#pragma unroll
    for (int j = 0; j < TN; j++) bfrag[j] = bptr[tcol * TN + j];

#pragma unroll
    for (int i = 0; i < TM; i++) {
        const int m = trow * TM + i;
        float* crow = C + (size_t)m * strideC + tcol * TN;
        float4 r0, r1;
        r0.x = acc[i][0] + bfrag[0];
        r0.y = acc[i][1] + bfrag[1];
        r0.z = acc[i][2] + bfrag[2];
        r0.w = acc[i][3] + bfrag[3];
        r1.x = acc[i][4] + bfrag[4];
        r1.y = acc[i][5] + bfrag[5];
        r1.z = acc[i][6] + bfrag[6];
        r1.w = acc[i][7] + bfrag[7];
        *(float4*)(crow + 0) = r0;
        *(float4*)(crow + 4) = r1;
    }
}

extern "C" void kernel_launch(void* const* d_in, const int* in_sizes, int n_in,
                              void* d_out, int out_size) {
    // Bind inputs by element count (robust to metadata ordering):
    //   x: 128*1024*512 = 67108864, gidx: 1024, weight: 16*512*512 = 4194304,
    //   bias: 16*512 = 8192
    const float* x    = nullptr;
    const void*  gidx = nullptr;
    const float* w    = nullptr;
    const float* b    = nullptr;
    for (int i = 0; i < n_in; i++) {
        switch (in_sizes[i]) {
            case 67108864: x    = (const float*)d_in[i]; break;
            case 1024:     gidx = d_in[i];               break;
            case 4194304:  w    = (const float*)d_in[i]; break;
            case 8192:     b    = (const float*)d_in[i]; break;
            default: break;
        }
    }
    // Positional fallback (setup_inputs dict order) if sniffing failed
    if (!x)    x    = (const float*)d_in[0];
    if (!gidx) gidx = d_in[1];
    if (!w)    w    = (const float*)d_in[2];
    if (!b)    b    = (const float*)d_in[3];

    float* out = (float*)d_out;  // [128,1024,512] f32

    decode_gidx_kernel<<<1, V_DIM>>>((const int*)gidx);

    dim3 grid(O_DIM / BN, 1, V_DIM);   // (4, 1, 1024)
    glinear_sgemm_kernel<<<grid, 256>>>(x, w, b, out);
}

// round 6
// speedup vs baseline: 2.0403x; 2.0403x over previous
#include <cuda_runtime.h>
#include <cuda_bf16.h>
#include <stdint.h>

#define B_DIM 128
#define V_DIM 1024
#define I_DIM 512
#define O_DIM 512
#define G_DIM 16

#define BM 128
#define BN 128
#define BK 32
#define NITER (I_DIM / BK)

#define SAPAD 40                 // bf16 row stride (80B = 20 banks -> conflict-free frag loads)
#define TILE_E (128 * SAPAD)     // bf16 elems per matrix tile per stage
#define SMEM_BYTES (2 * 4 * TILE_E * 2)   // 2 stages x 4 matrices x TILE_E bf16

// ---------------- group-index decode (int32/int64 robust) ----------------
__device__ int g_decoded[V_DIM];

__global__ void decode_gidx_kernel(const int* __restrict__ gidx_i32) {
    __shared__ int is_i32;
    const int v = threadIdx.x;
    if (v == 0) is_i32 = 0;
    __syncthreads();
    {
        const int w = gidx_i32[v];
        if (v & 1) { if (w != 0) atomicOr(&is_i32, 1); }
        else       { if (w < 0 || w >= G_DIM) atomicOr(&is_i32, 1); }
    }
    __syncthreads();
    int g = is_i32 ? gidx_i32[v] : gidx_i32[2 * v];
    if (g < 0) g = 0;
    if (g >= G_DIM) g = G_DIM - 1;
    g_decoded[v] = g;
}

// ---------------- helpers ----------------
__device__ __forceinline__ uint32_t pack_bf2(__nv_bfloat16 a, __nv_bfloat16 b) {
    return (uint32_t)__bfloat16_as_ushort(a) | ((uint32_t)__bfloat16_as_ushort(b) << 16);
}

__device__ __forceinline__ void cvt_hilo(float4 v, uint2& hi, uint2& lo) {
    __nv_bfloat16 h0 = __float2bfloat16_rn(v.x);
    __nv_bfloat16 h1 = __float2bfloat16_rn(v.y);
    __nv_bfloat16 h2 = __float2bfloat16_rn(v.z);
    __nv_bfloat16 h3 = __float2bfloat16_rn(v.w);
    __nv_bfloat16 l0 = __float2bfloat16_rn(v.x - __bfloat162float(h0));
    __nv_bfloat16 l1 = __float2bfloat16_rn(v.y - __bfloat162float(h1));
    __nv_bfloat16 l2 = __float2bfloat16_rn(v.z - __bfloat162float(h2));
    __nv_bfloat16 l3 = __float2bfloat16_rn(v.w - __bfloat162float(h3));
    hi.x = pack_bf2(h0, h1); hi.y = pack_bf2(h2, h3);
    lo.x = pack_bf2(l0, l1); lo.y = pack_bf2(l2, l3);
}

__device__ __forceinline__ void mma_bf16(float* d, const uint32_t* a, const uint32_t* b) {
    asm volatile(
        "mma.sync.aligned.m16n8k16.row.col.f32.bf16.bf16.f32 "
        "{%0,%1,%2,%3}, {%4,%5,%6,%7}, {%8,%9}, {%0,%1,%2,%3};"
        : "+f"(d[0]), "+f"(d[1]), "+f"(d[2]), "+f"(d[3])
        : "r"(a[0]), "r"(a[1]), "r"(a[2]), "r"(a[3]), "r"(b[0]), "r"(b[1]));
}

__device__ __forceinline__ uint32_t lds32(const __nv_bfloat16* p) {
    return *(const uint32_t*)p;
}

// ---------------- main kernel ----------------
__global__ void __launch_bounds__(256, 1) glinear_mma_kernel(
    const float* __restrict__ x,        // [B, V, I]
    const float* __restrict__ weight,   // [G, O, I]
    const float* __restrict__ bias,     // [G, O]
    float* __restrict__ out)            // [B, V, O]
{
    extern __shared__ __nv_bfloat16 sm[];

    const int tid = threadIdx.x;
    const int wid = tid >> 5;
    const int lid = tid & 31;
    const int gq  = lid >> 2;     // group-of-4 id (0..7)
    const int q   = lid & 3;      // lane-in-group
    const int wm  = wid >> 2;     // 0..1  (M direction, tile of 64)
    const int wn  = wid & 3;      // 0..3  (N direction, tile of 32)

    const int bid = blockIdx.x;
    const int v   = bid >> 2;
    const int nt  = bid & 3;
    const int grp = g_decoded[v];

    const float* Ap = x + (size_t)v * I_DIM;
    const float* Wp = weight + ((size_t)grp * O_DIM + (size_t)nt * BN) * I_DIM;
    const size_t strideA = (size_t)V_DIM * I_DIM;
    const size_t strideC = (size_t)V_DIM * O_DIM;

    // per-thread global load coords (same for A and B)
    int lmArr[4], lcArr[4];
#pragma unroll
    for (int j = 0; j < 4; j++) {
        int lin = tid + j * 256;          // 0..1023
        lmArr[j] = lin >> 3;              // row 0..127
        lcArr[j] = (lin & 7) * 4;         // f32 col {0,4,...,28}
    }

    float acc[4][4][4];
#pragma unroll
    for (int a = 0; a < 4; a++)
#pragma unroll
        for (int b = 0; b < 4; b++)
#pragma unroll
            for (int c = 0; c < 4; c++) acc[a][b][c] = 0.0f;

    float4 ra[4], rb[4];

    // prefetch iter 0
#pragma unroll
    for (int j = 0; j < 4; j++) {
        ra[j] = *(const float4*)(Ap + (size_t)lmArr[j] * strideA + lcArr[j]);
        rb[j] = *(const float4*)(Wp + (size_t)lmArr[j] * I_DIM + lcArr[j]);
    }
    // store stage 0
    {
        __nv_bfloat16* sAH = sm;
        __nv_bfloat16* sAL = sAH + TILE_E;
        __nv_bfloat16* sBH = sAH + 2 * TILE_E;
        __nv_bfloat16* sBL = sAH + 3 * TILE_E;
#pragma unroll
        for (int j = 0; j < 4; j++) {
            uint2 hi, lo;
            int off = lmArr[j] * SAPAD + lcArr[j];
            cvt_hilo(ra[j], hi, lo);
            *(uint2*)(sAH + off) = hi;
            *(uint2*)(sAL + off) = lo;
            cvt_hilo(rb[j], hi, lo);
            *(uint2*)(sBH + off) = hi;
            *(uint2*)(sBL + off) = lo;
        }
    }
    __syncthreads();

    for (int it = 0; it < NITER; it++) {
        // prefetch next k-block
        if (it + 1 < NITER) {
            const int k0 = (it + 1) * BK;
#pragma unroll
            for (int j = 0; j < 4; j++) {
                ra[j] = *(const float4*)(Ap + (size_t)lmArr[j] * strideA + k0 + lcArr[j]);
                rb[j] = *(const float4*)(Wp + (size_t)lmArr[j] * I_DIM + k0 + lcArr[j]);
            }
        }

        // compute from stage it&1
        {
            const __nv_bfloat16* sAH = sm + (size_t)(it & 1) * 4 * TILE_E;
            const __nv_bfloat16* sAL = sAH + TILE_E;
            const __nv_bfloat16* sBH = sAH + 2 * TILE_E;
            const __nv_bfloat16* sBL = sAH + 3 * TILE_E;

#pragma unroll
            for (int ks = 0; ks < 2; ks++) {
                const int kk = ks * 16 + 2 * q;
                uint32_t aH[4][4], aL[4][4], bH[4][2], bL[4][2];
#pragma unroll
                for (int mf = 0; mf < 4; mf++) {
                    const int base = (wm * 64 + mf * 16 + gq) * SAPAD + kk;
                    aH[mf][0] = lds32(sAH + base);
                    aH[mf][1] = lds32(sAH + base + 8 * SAPAD);
                    aH[mf][2] = lds32(sAH + base + 8);
                    aH[mf][3] = lds32(sAH + base + 8 * SAPAD + 8);
                    aL[mf][0] = lds32(sAL + base);
                    aL[mf][1] = lds32(sAL + base + 8 * SAPAD);
                    aL[mf][2] = lds32(sAL + base + 8);
                    aL[mf][3] = lds32(sAL + base + 8 * SAPAD + 8);
                }
#pragma unroll
                for (int nf = 0; nf < 4; nf++) {
                    const int base = (wn * 32 + nf * 8 + gq) * SAPAD + kk;
                    bH[nf][0] = lds32(sBH + base);
                    bH[nf][1] = lds32(sBH + base + 8);
                    bL[nf][0] = lds32(sBL + base);
                    bL[nf][1] = lds32(sBL + base + 8);
                }
#pragma unroll
                for (int mf = 0; mf < 4; mf++)
#pragma unroll
                    for (int nf = 0; nf < 4; nf++) {
                        mma_bf16(acc[mf][nf], aH[mf], bH[nf]);  // hi*hi
                        mma_bf16(acc[mf][nf], aH[mf], bL[nf]);  // hi*lo
                        mma_bf16(acc[mf][nf], aL[mf], bH[nf]);  // lo*hi
                    }
            }
        }

        // store next stage
        if (it + 1 < NITER) {
            __nv_bfloat16* sAH = sm + (size_t)((it + 1) & 1) * 4 * TILE_E;
            __nv_bfloat16* sAL = sAH + TILE_E;
            __nv_bfloat16* sBH = sAH + 2 * TILE_E;
            __nv_bfloat16* sBL = sAH + 3 * TILE_E;
#pragma unroll
            for (int j = 0; j < 4; j++) {
                uint2 hi, lo;
                int off = lmArr[j] * SAPAD + lcArr[j];
                cvt_hilo(ra[j], hi, lo);
                *(uint2*)(sAH + off) = hi;
                *(uint2*)(sAL + off) = lo;
                cvt_hilo(rb[j], hi, lo);
                *(uint2*)(sBH + off) = hi;
                *(uint2*)(sBL + off) = lo;
            }
        }
        __syncthreads();
    }

    // ---------------- epilogue: bias + direct stores ----------------
    const float* bptr = bias + (size_t)grp * O_DIM + (size_t)nt * BN;
#pragma unroll
    for (int nf = 0; nf < 4; nf++) {
        const int col = wn * 32 + nf * 8 + 2 * q;
        const float b0 = bptr[col];
        const float b1 = bptr[col + 1];
#pragma unroll
        for (int mf = 0; mf < 4; mf++) {
            const int row0 = wm * 64 + mf * 16 + gq;
            float2 v0, v1;
            v0.x = acc[mf][nf][0] + b0;
            v0.y = acc[mf][nf][1] + b1;
            v1.x = acc[mf][nf][2] + b0;
            v1.y = acc[mf][nf][3] + b1;
            float* o0 = out + (size_t)row0 * strideC + (size_t)v * O_DIM + nt * BN + col;
            *(float2*)o0 = v0;
            *(float2*)(o0 + 8 * strideC) = v1;
        }
    }
}

extern "C" void kernel_launch(void* const* d_in, const int* in_sizes, int n_in,
                              void* d_out, int out_size) {
    const float* x    = nullptr;
    const void*  gidx = nullptr;
    const float* w    = nullptr;
    const float* b    = nullptr;
    for (int i = 0; i < n_in; i++) {
        switch (in_sizes[i]) {
            case 67108864: x    = (const float*)d_in[i]; break;
            case 1024:     gidx = d_in[i];               break;
            case 4194304:  w    = (const float*)d_in[i]; break;
            case 8192:     b    = (const float*)d_in[i]; break;
            default: break;
        }
    }
    if (!x)    x    = (const float*)d_in[0];
    if (!gidx) gidx = d_in[1];
    if (!w)    w    = (const float*)d_in[2];
    if (!b)    b    = (const float*)d_in[3];

    float* out = (float*)d_out;

    static bool attr_done = false;
    if (!attr_done) {
        cudaFuncSetAttribute(glinear_mma_kernel,
                             cudaFuncAttributeMaxDynamicSharedMemorySize, SMEM_BYTES);
        attr_done = true;
    }

    decode_gidx_kernel<<<1, V_DIM>>>((const int*)gidx);
    glinear_mma_kernel<<<V_DIM * 4, 256, SMEM_BYTES>>>(x, w, b, out);
}

// round 7
// speedup vs baseline: 2.2426x; 1.0992x over previous
#include <cuda_runtime.h>
#include <cuda_bf16.h>
#include <stdint.h>

#define B_DIM 128
#define V_DIM 1024
#define I_DIM 512
#define O_DIM 512
#define G_DIM 16

#define BM 64
#define BN 128
#define BK 32
#define NITER (I_DIM / BK)

#define SAPAD 40                    // bf16 row stride: 80B = 20 banks -> conflict-free
#define A_TILE_E (64 * SAPAD)       // 2560 bf16
#define B_TILE_E (128 * SAPAD)      // 5120 bf16
#define STAGE_E (2 * A_TILE_E + 2 * B_TILE_E)   // AH,AL,BH,BL = 15360 bf16
#define SMEM_BYTES (2 * STAGE_E * 2)            // 2 stages -> 61440 B

// ---------------- group-index decode (int32/int64 robust) ----------------
__device__ int g_decoded[V_DIM];

__global__ void decode_gidx_kernel(const int* __restrict__ gidx_i32) {
    __shared__ int is_i32;
    const int v = threadIdx.x;
    if (v == 0) is_i32 = 0;
    __syncthreads();
    {
        const int w = gidx_i32[v];
        if (v & 1) { if (w != 0) atomicOr(&is_i32, 1); }
        else       { if (w < 0 || w >= G_DIM) atomicOr(&is_i32, 1); }
    }
    __syncthreads();
    int g = is_i32 ? gidx_i32[v] : gidx_i32[2 * v];
    if (g < 0) g = 0;
    if (g >= G_DIM) g = G_DIM - 1;
    g_decoded[v] = g;
}

// ---------------- helpers ----------------
__device__ __forceinline__ uint32_t pack_bf2(__nv_bfloat16 a, __nv_bfloat16 b) {
    return (uint32_t)__bfloat16_as_ushort(a) | ((uint32_t)__bfloat16_as_ushort(b) << 16);
}

__device__ __forceinline__ void cvt_hilo(float4 v, uint2& hi, uint2& lo) {
    __nv_bfloat16 h0 = __float2bfloat16_rn(v.x);
    __nv_bfloat16 h1 = __float2bfloat16_rn(v.y);
    __nv_bfloat16 h2 = __float2bfloat16_rn(v.z);
    __nv_bfloat16 h3 = __float2bfloat16_rn(v.w);
    __nv_bfloat16 l0 = __float2bfloat16_rn(v.x - __bfloat162float(h0));
    __nv_bfloat16 l1 = __float2bfloat16_rn(v.y - __bfloat162float(h1));
    __nv_bfloat16 l2 = __float2bfloat16_rn(v.z - __bfloat162float(h2));
    __nv_bfloat16 l3 = __float2bfloat16_rn(v.w - __bfloat162float(h3));
    hi.x = pack_bf2(h0, h1); hi.y = pack_bf2(h2, h3);
    lo.x = pack_bf2(l0, l1); lo.y = pack_bf2(l2, l3);
}

__device__ __forceinline__ void mma_bf16(float* d, const uint32_t* a, const uint32_t* b) {
    asm volatile(
        "mma.sync.aligned.m16n8k16.row.col.f32.bf16.bf16.f32 "
        "{%0,%1,%2,%3}, {%4,%5,%6,%7}, {%8,%9}, {%0,%1,%2,%3};"
        : "+f"(d[0]), "+f"(d[1]), "+f"(d[2]), "+f"(d[3])
        : "r"(a[0]), "r"(a[1]), "r"(a[2]), "r"(a[3]), "r"(b[0]), "r"(b[1]));
}

__device__ __forceinline__ uint32_t lds32(const __nv_bfloat16* p) {
    return *(const uint32_t*)p;
}

// ---------------- main kernel ----------------
__global__ void __launch_bounds__(256, 2) glinear_mma_kernel(
    const float* __restrict__ x,        // [B, V, I]
    const float* __restrict__ weight,   // [G, O, I]
    const float* __restrict__ bias,     // [G, O]
    float* __restrict__ out)            // [B, V, O]
{
    extern __shared__ __nv_bfloat16 sm[];

    const int tid = threadIdx.x;
    const int wid = tid >> 5;
    const int lid = tid & 31;
    const int gq  = lid >> 2;     // 0..7
    const int q   = lid & 3;      // 0..3
    const int wm  = wid >> 2;     // 0..1  (M tiles of 32)
    const int wn  = wid & 3;      // 0..3  (N tiles of 32)

    const int bid = blockIdx.x;
    const int v   = bid >> 3;
    const int rem = bid & 7;
    const int nt  = rem >> 1;     // 0..3 (N block of 128)
    const int mt  = rem & 1;      // 0..1 (M block of 64)
    const int grp = g_decoded[v];

    const float* Ap = x + (size_t)(mt * BM) * ((size_t)V_DIM * I_DIM) + (size_t)v * I_DIM;
    const float* Wp = weight + ((size_t)grp * O_DIM + (size_t)nt * BN) * I_DIM;
    const size_t strideA = (size_t)V_DIM * I_DIM;
    const size_t strideC = (size_t)V_DIM * O_DIM;

    // loader coords: A 2 float4/thread, B 4 float4/thread
    int amArr[2], acArr[2], bmArr[4], bcArr[4];
#pragma unroll
    for (int j = 0; j < 2; j++) {
        int lin = tid + j * 256;          // 0..511
        amArr[j] = lin >> 3;              // 0..63
        acArr[j] = (lin & 7) * 4;
    }
#pragma unroll
    for (int j = 0; j < 4; j++) {
        int lin = tid + j * 256;          // 0..1023
        bmArr[j] = lin >> 3;              // 0..127
        bcArr[j] = (lin & 7) * 4;
    }

    float acc[2][4][4];
#pragma unroll
    for (int a = 0; a < 2; a++)
#pragma unroll
        for (int b = 0; b < 4; b++)
#pragma unroll
            for (int c = 0; c < 4; c++) acc[a][b][c] = 0.0f;

    float4 ra[2], rb[4];

    // prefetch iter 0
#pragma unroll
    for (int j = 0; j < 2; j++)
        ra[j] = *(const float4*)(Ap + (size_t)amArr[j] * strideA + acArr[j]);
#pragma unroll
    for (int j = 0; j < 4; j++)
        rb[j] = *(const float4*)(Wp + (size_t)bmArr[j] * I_DIM + bcArr[j]);

    // store stage 0
    {
        __nv_bfloat16* sAH = sm;
        __nv_bfloat16* sAL = sAH + A_TILE_E;
        __nv_bfloat16* sBH = sAL + A_TILE_E;
        __nv_bfloat16* sBL = sBH + B_TILE_E;
#pragma unroll
        for (int j = 0; j < 2; j++) {
            uint2 hi, lo;
            int off = amArr[j] * SAPAD + acArr[j];
            cvt_hilo(ra[j], hi, lo);
            *(uint2*)(sAH + off) = hi;
            *(uint2*)(sAL + off) = lo;
        }
#pragma unroll
        for (int j = 0; j < 4; j++) {
            uint2 hi, lo;
            int off = bmArr[j] * SAPAD + bcArr[j];
            cvt_hilo(rb[j], hi, lo);
            *(uint2*)(sBH + off) = hi;
            *(uint2*)(sBL + off) = lo;
        }
    }
    __syncthreads();

    for (int it = 0; it < NITER; it++) {
        // prefetch next k-block into registers
        if (it + 1 < NITER) {
            const int k0 = (it + 1) * BK;
#pragma unroll
            for (int j = 0; j < 2; j++)
                ra[j] = *(const float4*)(Ap + (size_t)amArr[j] * strideA + k0 + acArr[j]);
#pragma unroll
            for (int j = 0; j < 4; j++)
                rb[j] = *(const float4*)(Wp + (size_t)bmArr[j] * I_DIM + k0 + bcArr[j]);
        }

        // compute from stage it&1
        {
            const __nv_bfloat16* sAH = sm + (size_t)(it & 1) * STAGE_E;
            const __nv_bfloat16* sAL = sAH + A_TILE_E;
            const __nv_bfloat16* sBH = sAL + A_TILE_E;
            const __nv_bfloat16* sBL = sBH + B_TILE_E;

#pragma unroll
            for (int ks = 0; ks < 2; ks++) {
                const int kk = ks * 16 + 2 * q;
                uint32_t aH[2][4], aL[2][4], bH[4][2], bL[4][2];
#pragma unroll
                for (int mf = 0; mf < 2; mf++) {
                    const int base = (wm * 32 + mf * 16 + gq) * SAPAD + kk;
                    aH[mf][0] = lds32(sAH + base);
                    aH[mf][1] = lds32(sAH + base + 8 * SAPAD);
                    aH[mf][2] = lds32(sAH + base + 8);
                    aH[mf][3] = lds32(sAH + base + 8 * SAPAD + 8);
                    aL[mf][0] = lds32(sAL + base);
                    aL[mf][1] = lds32(sAL + base + 8 * SAPAD);
                    aL[mf][2] = lds32(sAL + base + 8);
                    aL[mf][3] = lds32(sAL + base + 8 * SAPAD + 8);
                }
#pragma unroll
                for (int nf = 0; nf < 4; nf++) {
                    const int base = (wn * 32 + nf * 8 + gq) * SAPAD + kk;
                    bH[nf][0] = lds32(sBH + base);
                    bH[nf][1] = lds32(sBH + base + 8);
                    bL[nf][0] = lds32(sBL + base);
                    bL[nf][1] = lds32(sBL + base + 8);
                }
#pragma unroll
                for (int mf = 0; mf < 2; mf++)
#pragma unroll
                    for (int nf = 0; nf < 4; nf++) {
                        mma_bf16(acc[mf][nf], aH[mf], bH[nf]);  // hi*hi
                        mma_bf16(acc[mf][nf], aH[mf], bL[nf]);  // hi*lo
                        mma_bf16(acc[mf][nf], aL[mf], bH[nf]);  // lo*hi
                    }
            }
        }

        // store next stage
        if (it + 1 < NITER) {
            __nv_bfloat16* sAH = sm + (size_t)((it + 1) & 1) * STAGE_E;
            __nv_bfloat16* sAL = sAH + A_TILE_E;
            __nv_bfloat16* sBH = sAL + A_TILE_E;
            __nv_bfloat16* sBL = sBH + B_TILE_E;
#pragma unroll
            for (int j = 0; j < 2; j++) {
                uint2 hi, lo;
                int off = amArr[j] * SAPAD + acArr[j];
                cvt_hilo(ra[j], hi, lo);
                *(uint2*)(sAH + off) = hi;
                *(uint2*)(sAL + off) = lo;
            }
#pragma unroll
            for (int j = 0; j < 4; j++) {
                uint2 hi, lo;
                int off = bmArr[j] * SAPAD + bcArr[j];
                cvt_hilo(rb[j], hi, lo);
                *(uint2*)(sBH + off) = hi;
                *(uint2*)(sBL + off) = lo;
            }
        }
        __syncthreads();
    }

    // ---------------- epilogue: bias + direct stores ----------------
    const float* bptr = bias + (size_t)grp * O_DIM + (size_t)nt * BN;
#pragma unroll
    for (int nf = 0; nf < 4; nf++) {
        const int col = wn * 32 + nf * 8 + 2 * q;
        const float b0 = bptr[col];
        const float b1 = bptr[col + 1];
#pragma unroll
        for (int mf = 0; mf < 2; mf++) {
            const int row0 = mt * BM + wm * 32 + mf * 16 + gq;
            float2 v0, v1;
            v0.x = acc[mf][nf][0] + b0;
            v0.y = acc[mf][nf][1] + b1;
            v1.x = acc[mf][nf][2] + b0;
            v1.y = acc[mf][nf][3] + b1;
            float* o0 = out + (size_t)row0 * strideC + (size_t)v * O_DIM + nt * BN + col;
            *(float2*)o0 = v0;
            *(float2*)(o0 + 8 * strideC) = v1;
        }
    }
}

extern "C" void kernel_launch(void* const* d_in, const int* in_sizes, int n_in,
                              void* d_out, int out_size) {
    const float* x    = nullptr;
    const void*  gidx = nullptr;
    const float* w    = nullptr;
    const float* b    = nullptr;
    for (int i = 0; i < n_in; i++) {
        switch (in_sizes[i]) {
            case 67108864: x    = (const float*)d_in[i]; break;
            case 1024:     gidx = d_in[i];               break;
            case 4194304:  w    = (const float*)d_in[i]; break;
            case 8192:     b    = (const float*)d_in[i]; break;
            default: break;
        }
    }
    if (!x)    x    = (const float*)d_in[0];
    if (!gidx) gidx = d_in[1];
    if (!w)    w    = (const float*)d_in[2];
    if (!b)    b    = (const float*)d_in[3];

    float* out = (float*)d_out;

    static bool attr_done = false;
    if (!attr_done) {
        cudaFuncSetAttribute(glinear_mma_kernel,
                             cudaFuncAttributeMaxDynamicSharedMemorySize, SMEM_BYTES);
        attr_done = true;
    }

    decode_gidx_kernel<<<1, V_DIM>>>((const int*)gidx);
    glinear_mma_kernel<<<V_DIM * 8, 256, SMEM_BYTES>>>(x, w, b, out);
}

// round 9
// speedup vs baseline: 2.4414x; 1.0887x over previous
#include <cuda_runtime.h>
#include <cuda_bf16.h>
#include <stdint.h>

#define B_DIM 128
#define V_DIM 1024
#define I_DIM 512
#define O_DIM 512
#define G_DIM 16

#define BM 64
#define BN 128
#define BK 32
#define NITER (I_DIM / BK)

#define SAPAD 40                    // bf16 row stride: 80B = 20 banks -> conflict-free
#define A_TILE_E (64 * SAPAD)       // 2560 bf16
#define B_TILE_E (128 * SAPAD)      // 5120 bf16
#define STAGE_E (2 * A_TILE_E + 2 * B_TILE_E)   // AH,AL,BH,BL = 15360 bf16
#define SMEM_BYTES (2 * STAGE_E * 2)            // 2 stages -> 61440 B

// ---------------- group-index decode (int32/int64 robust) ----------------
__device__ int g_decoded[V_DIM];

__global__ void decode_gidx_kernel(const int* __restrict__ gidx_i32) {
    __shared__ int is_i32;
    const int v = threadIdx.x;
    if (v == 0) is_i32 = 0;
    __syncthreads();
    {
        const int w = gidx_i32[v];
        if (v & 1) { if (w != 0) atomicOr(&is_i32, 1); }
        else       { if (w < 0 || w >= G_DIM) atomicOr(&is_i32, 1); }
    }
    __syncthreads();
    int g = is_i32 ? gidx_i32[v] : gidx_i32[2 * v];
    if (g < 0) g = 0;
    if (g >= G_DIM) g = G_DIM - 1;
    g_decoded[v] = g;
}

// ---------------- helpers ----------------
__device__ __forceinline__ uint32_t pack_bf2(__nv_bfloat16 a, __nv_bfloat16 b) {
    return (uint32_t)__bfloat16_as_ushort(a) | ((uint32_t)__bfloat16_as_ushort(b) << 16);
}

__device__ __forceinline__ void cvt_hilo(float4 v, uint2& hi, uint2& lo) {
    __nv_bfloat16 h0 = __float2bfloat16_rn(v.x);
    __nv_bfloat16 h1 = __float2bfloat16_rn(v.y);
    __nv_bfloat16 h2 = __float2bfloat16_rn(v.z);
    __nv_bfloat16 h3 = __float2bfloat16_rn(v.w);
    __nv_bfloat16 l0 = __float2bfloat16_rn(v.x - __bfloat162float(h0));
    __nv_bfloat16 l1 = __float2bfloat16_rn(v.y - __bfloat162float(h1));
    __nv_bfloat16 l2 = __float2bfloat16_rn(v.z - __bfloat162float(h2));
    __nv_bfloat16 l3 = __float2bfloat16_rn(v.w - __bfloat162float(h3));
    hi.x = pack_bf2(h0, h1); hi.y = pack_bf2(h2, h3);
    lo.x = pack_bf2(l0, l1); lo.y = pack_bf2(l2, l3);
}

__device__ __forceinline__ void mma_bf16(float* d, const uint32_t* a, const uint32_t* b) {
    asm volatile(
        "mma.sync.aligned.m16n8k16.row.col.f32.bf16.bf16.f32 "
        "{%0,%1,%2,%3}, {%4,%5,%6,%7}, {%8,%9}, {%0,%1,%2,%3};"
        : "+f"(d[0]), "+f"(d[1]), "+f"(d[2]), "+f"(d[3])
        : "r"(a[0]), "r"(a[1]), "r"(a[2]), "r"(a[3]), "r"(b[0]), "r"(b[1]));
}

__device__ __forceinline__ void ldsm_x4(uint32_t& r0, uint32_t& r1, uint32_t& r2,
                                        uint32_t& r3, uint32_t addr) {
    asm volatile("ldmatrix.sync.aligned.m8n8.x4.shared.b16 {%0,%1,%2,%3}, [%4];"
                 : "=r"(r0), "=r"(r1), "=r"(r2), "=r"(r3) : "r"(addr));
}

// ---------------- main kernel ----------------
__global__ void __launch_bounds__(256, 2) glinear_mma_kernel(
    const float* __restrict__ x,        // [B, V, I]
    const float* __restrict__ weight,   // [G, O, I]
    const float* __restrict__ bias,     // [G, O]
    float* __restrict__ out)            // [B, V, O]
{
    extern __shared__ __nv_bfloat16 sm[];

    const int tid = threadIdx.x;
    const int wid = tid >> 5;
    const int lid = tid & 31;
    const int gq  = lid >> 2;     // 0..7
    const int q   = lid & 3;      // 0..3
    const int wm  = wid >> 2;     // 0..1  (M tiles of 32)
    const int wn  = wid & 3;      // 0..3  (N tiles of 32)

    const int bid = blockIdx.x;
    const int v   = bid >> 3;
    const int rem = bid & 7;
    const int nt  = rem >> 1;     // 0..3 (N block of 128)
    const int mt  = rem & 1;      // 0..1 (M block of 64)
    const int grp = g_decoded[v];

    const float* Ap = x + (size_t)(mt * BM) * ((size_t)V_DIM * I_DIM) + (size_t)v * I_DIM;
    const float* Wp = weight + ((size_t)grp * O_DIM + (size_t)nt * BN) * I_DIM;
    const size_t strideA = (size_t)V_DIM * I_DIM;
    const size_t strideC = (size_t)V_DIM * O_DIM;

    // loader coords: A 2 float4/thread, B 4 float4/thread
    int amArr[2], acArr[2], bmArr[4], bcArr[4];
#pragma unroll
    for (int j = 0; j < 2; j++) {
        int lin = tid + j * 256;          // 0..511
        amArr[j] = lin >> 3;              // 0..63
        acArr[j] = (lin & 7) * 4;
    }
#pragma unroll
    for (int j = 0; j < 4; j++) {
        int lin = tid + j * 256;          // 0..1023
        bmArr[j] = lin >> 3;              // 0..127
        bcArr[j] = (lin & 7) * 4;
    }

    // ldmatrix per-lane base addresses (byte offsets within a stage)
    const uint32_t smBase = (uint32_t)__cvta_generic_to_shared(sm);
    // A: quadrants (m0-7,k0-7),(m8-15,k0-7),(m0-7,k8-15),(m8-15,k8-15)
    const int aRow = wm * 32 + (lid & 7) + ((lid >> 3) & 1) * 8;
    const int aK   = (lid >> 4) * 8;
    const uint32_t aOff = (uint32_t)((aRow * SAPAD + aK) * 2);
    // B x4 covers two n8 tiles: (n0-7,k0-7),(n0-7,k8-15),(n8-15,k0-7),(n8-15,k8-15)
    const int bRow = wn * 32 + (lid & 7) + (lid >> 4) * 8;
    const int bK   = ((lid >> 3) & 1) * 8;
    const uint32_t bOff = (uint32_t)((bRow * SAPAD + bK) * 2);

    const uint32_t AH_OFF = 0;
    const uint32_t AL_OFF = A_TILE_E * 2;
    const uint32_t BH_OFF = 2 * A_TILE_E * 2;
    const uint32_t BL_OFF = BH_OFF + B_TILE_E * 2;

    float acc[2][4][4];
#pragma unroll
    for (int a = 0; a < 2; a++)
#pragma unroll
        for (int b = 0; b < 4; b++)
#pragma unroll
            for (int c = 0; c < 4; c++) acc[a][b][c] = 0.0f;

    float4 ra[2], rb[4];

    // prefetch iter 0
#pragma unroll
    for (int j = 0; j < 2; j++)
        ra[j] = *(const float4*)(Ap + (size_t)amArr[j] * strideA + acArr[j]);
#pragma unroll
    for (int j = 0; j < 4; j++)
        rb[j] = *(const float4*)(Wp + (size_t)bmArr[j] * I_DIM + bcArr[j]);

    // store stage 0
    {
        __nv_bfloat16* sAH = sm;
        __nv_bfloat16* sAL = sAH + A_TILE_E;
        __nv_bfloat16* sBH = sAL + A_TILE_E;
        __nv_bfloat16* sBL = sBH + B_TILE_E;
#pragma unroll
        for (int j = 0; j < 2; j++) {
            uint2 hi, lo;
            int off = amArr[j] * SAPAD + acArr[j];
            cvt_hilo(ra[j], hi, lo);
            *(uint2*)(sAH + off) = hi;
            *(uint2*)(sAL + off) = lo;
        }
#pragma unroll
        for (int j = 0; j < 4; j++) {
            uint2 hi, lo;
            int off = bmArr[j] * SAPAD + bcArr[j];
            cvt_hilo(rb[j], hi, lo);
            *(uint2*)(sBH + off) = hi;
            *(uint2*)(sBL + off) = lo;
        }
    }
    __syncthreads();

    for (int it = 0; it < NITER; it++) {
        // prefetch next k-block into registers
        if (it + 1 < NITER) {
            const int k0 = (it + 1) * BK;
#pragma unroll
            for (int j = 0; j < 2; j++)
                ra[j] = *(const float4*)(Ap + (size_t)amArr[j] * strideA + k0 + acArr[j]);
#pragma unroll
            for (int j = 0; j < 4; j++)
                rb[j] = *(const float4*)(Wp + (size_t)bmArr[j] * I_DIM + k0 + bcArr[j]);
        }

        // compute from stage it&1 via ldmatrix
        {
            const uint32_t stage = smBase + (uint32_t)(it & 1) * (STAGE_E * 2);
            const uint32_t aAddr = stage + aOff;
            const uint32_t bAddr = stage + bOff;

#pragma unroll
            for (int ks = 0; ks < 2; ks++) {
                const uint32_t kd = (uint32_t)(ks * 32);   // 16 bf16 = 32 B
                uint32_t aH[2][4], aL[2][4], bH[4][2], bL[4][2];
#pragma unroll
                for (int mf = 0; mf < 2; mf++) {
                    const uint32_t md = (uint32_t)(mf * 16 * SAPAD * 2);
                    ldsm_x4(aH[mf][0], aH[mf][1], aH[mf][2], aH[mf][3],
                            aAddr + AH_OFF + md + kd);
                    ldsm_x4(aL[mf][0], aL[mf][1], aL[mf][2], aL[mf][3],
                            aAddr + AL_OFF + md + kd);
                }
#pragma unroll
                for (int nfp = 0; nfp < 2; nfp++) {
                    const uint32_t nd = (uint32_t)(nfp * 16 * SAPAD * 2);
                    ldsm_x4(bH[nfp * 2][0], bH[nfp * 2][1], bH[nfp * 2 + 1][0],
                            bH[nfp * 2 + 1][1], bAddr + BH_OFF + nd + kd);
                    ldsm_x4(bL[nfp * 2][0], bL[nfp * 2][1], bL[nfp * 2 + 1][0],
                            bL[nfp * 2 + 1][1], bAddr + BL_OFF + nd + kd);
                }
#pragma unroll
                for (int mf = 0; mf < 2; mf++)
#pragma unroll
                    for (int nf = 0; nf < 4; nf++) {
                        mma_bf16(acc[mf][nf], aH[mf], bH[nf]);  // hi*hi
                        mma_bf16(acc[mf][nf], aH[mf], bL[nf]);  // hi*lo
                        mma_bf16(acc[mf][nf], aL[mf], bH[nf]);  // lo*hi
                    }
            }
        }

        // store next stage
        if (it + 1 < NITER) {
            __nv_bfloat16* sAH = sm + (size_t)((it + 1) & 1) * STAGE_E;
            __nv_bfloat16* sAL = sAH + A_TILE_E;
            __nv_bfloat16* sBH = sAL + A_TILE_E;
            __nv_bfloat16* sBL = sBH + B_TILE_E;
#pragma unroll
            for (int j = 0; j < 2; j++) {
                uint2 hi, lo;
                int off = amArr[j] * SAPAD + acArr[j];
                cvt_hilo(ra[j], hi, lo);
                *(uint2*)(sAH + off) = hi;
                *(uint2*)(sAL + off) = lo;
            }
#pragma unroll
            for (int j = 0; j < 4; j++) {
                uint2 hi, lo;
                int off = bmArr[j] * SAPAD + bcArr[j];
                cvt_hilo(rb[j], hi, lo);
                *(uint2*)(sBH + off) = hi;
                *(uint2*)(sBL + off) = lo;
            }
        }
        __syncthreads();
    }

    // ---------------- epilogue: bias + direct stores ----------------
    const float* bptr = bias + (size_t)grp * O_DIM + (size_t)nt * BN;
#pragma unroll
    for (int nf = 0; nf < 4; nf++) {
        const int col = wn * 32 + nf * 8 + 2 * q;
        const float b0 = bptr[col];
        const float b1 = bptr[col + 1];
#pragma unroll
        for (int mf = 0; mf < 2; mf++) {
            const int row0 = mt * BM + wm * 32 + mf * 16 + gq;
            float2 v0, v1;
            v0.x = acc[mf][nf][0] + b0;
            v0.y = acc[mf][nf][1] + b1;
            v1.x = acc[mf][nf][2] + b0;
            v1.y = acc[mf][nf][3] + b1;
            float* o0 = out + (size_t)row0 * strideC + (size_t)v * O_DIM + nt * BN + col;
            *(float2*)o0 = v0;
            *(float2*)(o0 + 8 * strideC) = v1;
        }
    }
}

extern "C" void kernel_launch(void* const* d_in, const int* in_sizes, int n_in,
                              void* d_out, int out_size) {
    const float* x    = nullptr;
    const void*  gidx = nullptr;
    const float* w    = nullptr;
    const float* b    = nullptr;
    for (int i = 0; i < n_in; i++) {
        switch (in_sizes[i]) {
            case 67108864: x    = (const float*)d_in[i]; break;
            case 1024:     gidx = d_in[i];               break;
            case 4194304:  w    = (const float*)d_in[i]; break;
            case 8192:     b    = (const float*)d_in[i]; break;
            default: break;
        }
    }
    if (!x)    x    = (const float*)d_in[0];
    if (!gidx) gidx = d_in[1];
    if (!w)    w    = (const float*)d_in[2];
    if (!b)    b    = (const float*)d_in[3];

    float* out = (float*)d_out;

    static bool attr_done = false;
    if (!attr_done) {
        cudaFuncSetAttribute(glinear_mma_kernel,
                             cudaFuncAttributeMaxDynamicSharedMemorySize, SMEM_BYTES);
        attr_done = true;
    }

    decode_gidx_kernel<<<1, V_DIM>>>((const int*)gidx);
    glinear_mma_kernel<<<V_DIM * 8, 256, SMEM_BYTES>>>(x, w, b, out);
}

// round 11
// speedup vs baseline: 2.4427x; 1.0005x over previous
#include <cuda_runtime.h>
#include <cuda_bf16.h>
#include <stdint.h>

#define B_DIM 128
#define V_DIM 1024
#define I_DIM 512
#define O_DIM 512
#define G_DIM 16

#define BM 64
#define BN 128
#define BK 32
#define NITER (I_DIM / BK)

#define SAPAD 40                    // bf16 row stride: 80B (16B-aligned rows, conflict-free LDSM)
#define A_TILE_E (64 * SAPAD)       // 2560 bf16
#define B_TILE_E (128 * SAPAD)      // 5120 bf16
#define STAGE_E (2 * A_TILE_E + 2 * B_TILE_E)   // AH,AL,BH,BL = 15360 bf16
#define SMEM_BYTES (2 * STAGE_E * 2)            // 2 stages -> 61440 B

// ---------------- static scratch: pre-split weights (bf16 hi/lo) ----------------
__device__ __nv_bfloat16 wh_buf[G_DIM * O_DIM * I_DIM];   // 8 MB
__device__ __nv_bfloat16 wl_buf[G_DIM * O_DIM * I_DIM];   // 8 MB

// ---------------- group-index decode (int32/int64 robust) ----------------
__device__ int g_decoded[V_DIM];

__global__ void decode_gidx_kernel(const int* __restrict__ gidx_i32) {
    __shared__ int is_i32;
    const int v = threadIdx.x;
    if (v == 0) is_i32 = 0;
    __syncthreads();
    {
        const int w = gidx_i32[v];
        if (v & 1) { if (w != 0) atomicOr(&is_i32, 1); }
        else       { if (w < 0 || w >= G_DIM) atomicOr(&is_i32, 1); }
    }
    __syncthreads();
    int g = is_i32 ? gidx_i32[v] : gidx_i32[2 * v];
    if (g < 0) g = 0;
    if (g >= G_DIM) g = G_DIM - 1;
    g_decoded[v] = g;
}

// ---------------- helpers ----------------
__device__ __forceinline__ uint32_t pack_bf2(__nv_bfloat16 a, __nv_bfloat16 b) {
    return (uint32_t)__bfloat16_as_ushort(a) | ((uint32_t)__bfloat16_as_ushort(b) << 16);
}

__device__ __forceinline__ void cvt_hilo(float4 v, uint2& hi, uint2& lo) {
    __nv_bfloat16 h0 = __float2bfloat16_rn(v.x);
    __nv_bfloat16 h1 = __float2bfloat16_rn(v.y);
    __nv_bfloat16 h2 = __float2bfloat16_rn(v.z);
    __nv_bfloat16 h3 = __float2bfloat16_rn(v.w);
    __nv_bfloat16 l0 = __float2bfloat16_rn(v.x - __bfloat162float(h0));
    __nv_bfloat16 l1 = __float2bfloat16_rn(v.y - __bfloat162float(h1));
    __nv_bfloat16 l2 = __float2bfloat16_rn(v.z - __bfloat162float(h2));
    __nv_bfloat16 l3 = __float2bfloat16_rn(v.w - __bfloat162float(h3));
    hi.x = pack_bf2(h0, h1); hi.y = pack_bf2(h2, h3);
    lo.x = pack_bf2(l0, l1); lo.y = pack_bf2(l2, l3);
}

__device__ __forceinline__ void mma_bf16(float* d, const uint32_t* a, const uint32_t* b) {
    asm volatile(
        "mma.sync.aligned.m16n8k16.row.col.f32.bf16.bf16.f32 "
        "{%0,%1,%2,%3}, {%4,%5,%6,%7}, {%8,%9}, {%0,%1,%2,%3};"
        : "+f"(d[0]), "+f"(d[1]), "+f"(d[2]), "+f"(d[3])
        : "r"(a[0]), "r"(a[1]), "r"(a[2]), "r"(a[3]), "r"(b[0]), "r"(b[1]));
}

__device__ __forceinline__ void ldsm_x4(uint32_t& r0, uint32_t& r1, uint32_t& r2,
                                        uint32_t& r3, uint32_t addr) {
    asm volatile("ldmatrix.sync.aligned.m8n8.x4.shared.b16 {%0,%1,%2,%3}, [%4];"
                 : "=r"(r0), "=r"(r1), "=r"(r2), "=r"(r3) : "r"(addr));
}

__device__ __forceinline__ void cp_async16(uint32_t smem_addr, const void* gptr) {
    asm volatile("cp.async.cg.shared.global [%0], [%1], 16;"
                 :: "r"(smem_addr), "l"(gptr) : "memory");
}
__device__ __forceinline__ void cp_commit() {
    asm volatile("cp.async.commit_group;" ::: "memory");
}
__device__ __forceinline__ void cp_wait0() {
    asm volatile("cp.async.wait_group 0;" ::: "memory");
}

// ---------------- weight pre-split kernel (runs every launch; idempotent) ------
__global__ void convert_w_kernel(const float* __restrict__ w) {
    const int i = blockIdx.x * 256 + threadIdx.x;   // indexes float4 (1M total)
    float4 v = ((const float4*)w)[i];
    uint2 hi, lo;
    cvt_hilo(v, hi, lo);
    ((uint2*)wh_buf)[i] = hi;
    ((uint2*)wl_buf)[i] = lo;
}

// ---------------- main kernel ----------------
__global__ void __launch_bounds__(256, 2) glinear_mma_kernel(
    const float* __restrict__ x,        // [B, V, I]
    const float* __restrict__ bias,     // [G, O]
    float* __restrict__ out)            // [B, V, O]
{
    extern __shared__ __nv_bfloat16 sm[];

    const int tid = threadIdx.x;
    const int wid = tid >> 5;
    const int lid = tid & 31;
    const int q   = lid & 3;      // 0..3
    const int gq  = lid >> 2;     // 0..7
    const int wm  = wid >> 2;     // 0..1  (M tiles of 32)
    const int wn  = wid & 3;      // 0..3  (N tiles of 32)

    const int bid = blockIdx.x;
    const int v   = bid >> 3;
    const int rem = bid & 7;
    const int nt  = rem >> 1;     // 0..3 (N block of 128)
    const int mt  = rem & 1;      // 0..1 (M block of 64)
    const int grp = g_decoded[v];

    const float* Ap = x + (size_t)(mt * BM) * ((size_t)V_DIM * I_DIM) + (size_t)v * I_DIM;
    const __nv_bfloat16* Wh = wh_buf + ((size_t)grp * O_DIM + (size_t)nt * BN) * I_DIM;
    const __nv_bfloat16* Wl = wl_buf + ((size_t)grp * O_DIM + (size_t)nt * BN) * I_DIM;
    const size_t strideA = (size_t)V_DIM * I_DIM;
    const size_t strideC = (size_t)V_DIM * O_DIM;

    // ---- A loader: one 8-elem chunk per thread (row 0..63, kchunk 0..3) ----
    const int aLRow = tid >> 2;          // 0..63
    const int aLK   = (tid & 3) * 8;     // {0,8,16,24}

    // ---- B cp.async coords: 4 chunks of 16B per thread ----
    // cid = tid + j*256 (0..1023): [half(hi/lo)][row 0..127][kchunk 0..3]
    const uint32_t smBase = (uint32_t)__cvta_generic_to_shared(sm);

    const uint32_t AH_OFF = 0;
    const uint32_t AL_OFF = A_TILE_E * 2;
    const uint32_t BH_OFF = 2 * A_TILE_E * 2;
    const uint32_t BL_OFF = BH_OFF + B_TILE_E * 2;

    // ldmatrix per-lane base addresses (byte offsets within a stage)
    const int aRow = wm * 32 + (lid & 7) + ((lid >> 3) & 1) * 8;
    const int aK   = (lid >> 4) * 8;
    const uint32_t aOff = (uint32_t)((aRow * SAPAD + aK) * 2);
    const int bRow = wn * 32 + (lid & 7) + (lid >> 4) * 8;
    const int bK   = ((lid >> 3) & 1) * 8;
    const uint32_t bOff = (uint32_t)((bRow * SAPAD + bK) * 2);

    float acc[2][4][4];
#pragma unroll
    for (int a = 0; a < 2; a++)
#pragma unroll
        for (int b = 0; b < 4; b++)
#pragma unroll
            for (int c = 0; c < 4; c++) acc[a][b][c] = 0.0f;

    // ---- fill stage 0 ----
    {
        // B via cp.async (bypasses L1, no STS)
#pragma unroll
        for (int j = 0; j < 4; j++) {
            const int cid  = tid + j * 256;
            const int half = cid >> 9;            // 0 hi, 1 lo
            const int r    = (cid >> 2) & 127;
            const int kc   = cid & 3;
            const uint32_t dst = smBase + (half ? BL_OFF : BH_OFF)
                               + (uint32_t)((r * SAPAD + kc * 8) * 2);
            const __nv_bfloat16* src = (half ? Wl : Wh) + (size_t)r * I_DIM + kc * 8;
            cp_async16(dst, src);
        }
        cp_commit();
        // A via LDG + convert + STS.128
        float4 va0 = *(const float4*)(Ap + (size_t)aLRow * strideA + aLK);
        float4 va1 = *(const float4*)(Ap + (size_t)aLRow * strideA + aLK + 4);
        uint2 h0, l0, h1, l1;
        cvt_hilo(va0, h0, l0);
        cvt_hilo(va1, h1, l1);
        const int off = aLRow * SAPAD + aLK;
        *(uint4*)(sm + off)            = make_uint4(h0.x, h0.y, h1.x, h1.y);
        *(uint4*)(sm + A_TILE_E + off) = make_uint4(l0.x, l0.y, l1.x, l1.y);
        cp_wait0();
    }
    __syncthreads();

    float4 ra0, ra1;

    for (int it = 0; it < NITER; it++) {
        // issue next-stage B cp.async + prefetch next A into registers
        if (it + 1 < NITER) {
            const int k0n = (it + 1) * BK;
            const uint32_t nstage = smBase + (uint32_t)((it + 1) & 1) * (STAGE_E * 2);
#pragma unroll
            for (int j = 0; j < 4; j++) {
                const int cid  = tid + j * 256;
                const int half = cid >> 9;
                const int r    = (cid >> 2) & 127;
                const int kc   = cid & 3;
                const uint32_t dst = nstage + (half ? BL_OFF : BH_OFF) - smBase + smBase
                                   + (uint32_t)((r * SAPAD + kc * 8) * 2);
                const __nv_bfloat16* src = (half ? Wl : Wh) + (size_t)r * I_DIM + k0n + kc * 8;
                cp_async16(dst, src);
            }
            cp_commit();
            ra0 = *(const float4*)(Ap + (size_t)aLRow * strideA + k0n + aLK);
            ra1 = *(const float4*)(Ap + (size_t)aLRow * strideA + k0n + aLK + 4);
        }

        // compute current stage via ldmatrix + mma
        {
            const uint32_t stage = smBase + (uint32_t)(it & 1) * (STAGE_E * 2);
            const uint32_t aAddr = stage + aOff;
            const uint32_t bAddr = stage + bOff;

#pragma unroll
            for (int ks = 0; ks < 2; ks++) {
                const uint32_t kd = (uint32_t)(ks * 32);   // 16 bf16 = 32 B
                uint32_t aH[2][4], aL[2][4], bH[4][2], bL[4][2];
#pragma unroll
                for (int mf = 0; mf < 2; mf++) {
                    const uint32_t md = (uint32_t)(mf * 16 * SAPAD * 2);
                    ldsm_x4(aH[mf][0], aH[mf][1], aH[mf][2], aH[mf][3],
                            aAddr + AH_OFF + md + kd);
                    ldsm_x4(aL[mf][0], aL[mf][1], aL[mf][2], aL[mf][3],
                            aAddr + AL_OFF + md + kd);
                }
#pragma unroll
                for (int nfp = 0; nfp < 2; nfp++) {
                    const uint32_t nd = (uint32_t)(nfp * 16 * SAPAD * 2);
                    ldsm_x4(bH[nfp * 2][0], bH[nfp * 2][1], bH[nfp * 2 + 1][0],
                            bH[nfp * 2 + 1][1], bAddr + BH_OFF + nd + kd);
                    ldsm_x4(bL[nfp * 2][0], bL[nfp * 2][1], bL[nfp * 2 + 1][0],
                            bL[nfp * 2 + 1][1], bAddr + BL_OFF + nd + kd);
                }
#pragma unroll
                for (int mf = 0; mf < 2; mf++)
#pragma unroll
                    for (int nf = 0; nf < 4; nf++) {
                        mma_bf16(acc[mf][nf], aH[mf], bH[nf]);  // hi*hi
                        mma_bf16(acc[mf][nf], aH[mf], bL[nf]);  // hi*lo
                        mma_bf16(acc[mf][nf], aL[mf], bH[nf]);  // lo*hi
                    }
            }
        }

        // store next-stage A, then wait for B cp.async and sync
        if (it + 1 < NITER) {
            __nv_bfloat16* nsm = sm + (size_t)((it + 1) & 1) * STAGE_E;
            uint2 h0, l0, h1, l1;
            cvt_hilo(ra0, h0, l0);
            cvt_hilo(ra1, h1, l1);
            const int off = aLRow * SAPAD + aLK;
            *(uint4*)(nsm + off)            = make_uint4(h0.x, h0.y, h1.x, h1.y);
            *(uint4*)(nsm + A_TILE_E + off) = make_uint4(l0.x, l0.y, l1.x, l1.y);
            cp_wait0();
        }
        __syncthreads();
    }

    // ---------------- epilogue: bias + direct stores ----------------
    const float* bptr = bias + (size_t)grp * O_DIM + (size_t)nt * BN;
#pragma unroll
    for (int nf = 0; nf < 4; nf++) {
        const int col = wn * 32 + nf * 8 + 2 * q;
        const float b0 = bptr[col];
        const float b1 = bptr[col + 1];
#pragma unroll
        for (int mf = 0; mf < 2; mf++) {
            const int row0 = mt * BM + wm * 32 + mf * 16 + gq;
            float2 v0, v1;
            v0.x = acc[mf][nf][0] + b0;
            v0.y = acc[mf][nf][1] + b1;
            v1.x = acc[mf][nf][2] + b0;
            v1.y = acc[mf][nf][3] + b1;
            float* o0 = out + (size_t)row0 * strideC + (size_t)v * O_DIM + nt * BN + col;
            *(float2*)o0 = v0;
            *(float2*)(o0 + 8 * strideC) = v1;
        }
    }
}

extern "C" void kernel_launch(void* const* d_in, const int* in_sizes, int n_in,
                              void* d_out, int out_size) {
    const float* x    = nullptr;
    const void*  gidx = nullptr;
    const float* w    = nullptr;
    const float* b    = nullptr;
    for (int i = 0; i < n_in; i++) {
        switch (in_sizes[i]) {
            case 67108864: x    = (const float*)d_in[i]; break;
            case 1024:     gidx = d_in[i];               break;
            case 4194304:  w    = (const float*)d_in[i]; break;
            case 8192:     b    = (const float*)d_in[i]; break;
            default: break;
        }
    }
    if (!x)    x    = (const float*)d_in[0];
    if (!gidx) gidx = d_in[1];
    if (!w)    w    = (const float*)d_in[2];
    if (!b)    b    = (const float*)d_in[3];

    float* out = (float*)d_out;

    static bool attr_done = false;
    if (!attr_done) {
        cudaFuncSetAttribute(glinear_mma_kernel,
                             cudaFuncAttributeMaxDynamicSharedMemorySize, SMEM_BYTES);
        attr_done = true;
    }

    decode_gidx_kernel<<<1, V_DIM>>>((const int*)gidx);
    convert_w_kernel<<<(G_DIM * O_DIM * I_DIM / 4) / 256, 256>>>(w);
    glinear_mma_kernel<<<V_DIM * 8, 256, SMEM_BYTES>>>(x, b, out);
}

// round 13
// speedup vs baseline: 3.2024x; 1.3110x over previous
#include <cuda_runtime.h>
#include <cuda_fp16.h>
#include <stdint.h>

#define B_DIM 128
#define V_DIM 1024
#define I_DIM 512
#define O_DIM 512
#define G_DIM 16

#define BM 64
#define BN 128
#define BK 32
#define NITER (I_DIM / BK)

#define SAPAD 40                    // fp16 row stride: 80B (16B-aligned rows, conflict-free LDSM)
#define A_TILE_E (64 * SAPAD)       // 2560 halves
#define B_TILE_E (128 * SAPAD)      // 5120 halves
#define STAGE_E (2 * A_TILE_E + B_TILE_E)       // AH,AL,B = 10240 halves
#define SMEM_BYTES (2 * STAGE_E * 2)            // 2 stages -> 40960 B

// ---------------- static scratch: pre-converted fp16 weights ----------------
__device__ __half wh_buf[G_DIM * O_DIM * I_DIM];   // 8 MB

// ---------------- group-index decode (int32/int64 robust) ----------------
__device__ int g_decoded[V_DIM];

__global__ void decode_gidx_kernel(const int* __restrict__ gidx_i32) {
    __shared__ int is_i32;
    const int v = threadIdx.x;
    if (v == 0) is_i32 = 0;
    __syncthreads();
    {
        const int w = gidx_i32[v];
        if (v & 1) { if (w != 0) atomicOr(&is_i32, 1); }
        else       { if (w < 0 || w >= G_DIM) atomicOr(&is_i32, 1); }
    }
    __syncthreads();
    int g = is_i32 ? gidx_i32[v] : gidx_i32[2 * v];
    if (g < 0) g = 0;
    if (g >= G_DIM) g = G_DIM - 1;
    g_decoded[v] = g;
}

// ---------------- helpers ----------------
__device__ __forceinline__ uint32_t pack_h2(__half a, __half b) {
    return (uint32_t)__half_as_ushort(a) | ((uint32_t)__half_as_ushort(b) << 16);
}

// split float4 into fp16 hi + fp16 residual lo
__device__ __forceinline__ void cvt_hilo_f16(float4 v, uint2& hi, uint2& lo) {
    __half h0 = __float2half_rn(v.x);
    __half h1 = __float2half_rn(v.y);
    __half h2 = __float2half_rn(v.z);
    __half h3 = __float2half_rn(v.w);
    __half l0 = __float2half_rn(v.x - __half2float(h0));
    __half l1 = __float2half_rn(v.y - __half2float(h1));
    __half l2 = __float2half_rn(v.z - __half2float(h2));
    __half l3 = __float2half_rn(v.w - __half2float(h3));
    hi.x = pack_h2(h0, h1); hi.y = pack_h2(h2, h3);
    lo.x = pack_h2(l0, l1); lo.y = pack_h2(l2, l3);
}

// single fp16 conversion of float4
__device__ __forceinline__ uint2 cvt_f16(float4 v) {
    uint2 r;
    r.x = pack_h2(__float2half_rn(v.x), __float2half_rn(v.y));
    r.y = pack_h2(__float2half_rn(v.z), __float2half_rn(v.w));
    return r;
}

__device__ __forceinline__ void mma_f16(float* d, const uint32_t* a, const uint32_t* b) {
    asm volatile(
        "mma.sync.aligned.m16n8k16.row.col.f32.f16.f16.f32 "
        "{%0,%1,%2,%3}, {%4,%5,%6,%7}, {%8,%9}, {%0,%1,%2,%3};"
        : "+f"(d[0]), "+f"(d[1]), "+f"(d[2]), "+f"(d[3])
        : "r"(a[0]), "r"(a[1]), "r"(a[2]), "r"(a[3]), "r"(b[0]), "r"(b[1]));
}

__device__ __forceinline__ void ldsm_x4(uint32_t& r0, uint32_t& r1, uint32_t& r2,
                                        uint32_t& r3, uint32_t addr) {
    asm volatile("ldmatrix.sync.aligned.m8n8.x4.shared.b16 {%0,%1,%2,%3}, [%4];"
                 : "=r"(r0), "=r"(r1), "=r"(r2), "=r"(r3) : "r"(addr));
}

__device__ __forceinline__ void cp_async16(uint32_t smem_addr, const void* gptr) {
    asm volatile("cp.async.cg.shared.global [%0], [%1], 16;"
                 :: "r"(smem_addr), "l"(gptr) : "memory");
}
__device__ __forceinline__ void cp_commit() {
    asm volatile("cp.async.commit_group;" ::: "memory");
}
__device__ __forceinline__ void cp_wait0() {
    asm volatile("cp.async.wait_group 0;" ::: "memory");
}

// ---------------- weight fp16-convert prepass (idempotent) ------
__global__ void convert_w_kernel(const float* __restrict__ w) {
    const int i = blockIdx.x * 256 + threadIdx.x;   // indexes float4 (1M total)
    float4 v = ((const float4*)w)[i];
    ((uint2*)wh_buf)[i] = cvt_f16(v);
}

// ---------------- main kernel ----------------
__global__ void __launch_bounds__(256, 2) glinear_mma_kernel(
    const float* __restrict__ x,        // [B, V, I]
    const float* __restrict__ bias,     // [G, O]
    float* __restrict__ out)            // [B, V, O]
{
    extern __shared__ __half sm[];

    const int tid = threadIdx.x;
    const int wid = tid >> 5;
    const int lid = tid & 31;
    const int q   = lid & 3;      // 0..3
    const int gq  = lid >> 2;     // 0..7
    const int wm  = wid >> 2;     // 0..1  (M tiles of 32)
    const int wn  = wid & 3;      // 0..3  (N tiles of 32)

    const int bid = blockIdx.x;
    const int v   = bid >> 3;
    const int rem = bid & 7;
    const int nt  = rem >> 1;     // 0..3 (N block of 128)
    const int mt  = rem & 1;      // 0..1 (M block of 64)
    const int grp = g_decoded[v];

    const float* Ap = x + (size_t)(mt * BM) * ((size_t)V_DIM * I_DIM) + (size_t)v * I_DIM;
    const __half* Wp = wh_buf + ((size_t)grp * O_DIM + (size_t)nt * BN) * I_DIM;
    const size_t strideA = (size_t)V_DIM * I_DIM;
    const size_t strideC = (size_t)V_DIM * O_DIM;

    // ---- A loader: one 8-elem chunk per thread (row 0..63, kchunk 0..3) ----
    const int aLRow = tid >> 2;          // 0..63
    const int aLK   = (tid & 3) * 8;     // {0,8,16,24}

    const uint32_t smBase = (uint32_t)__cvta_generic_to_shared(sm);

    const uint32_t AH_OFF = 0;
    const uint32_t AL_OFF = A_TILE_E * 2;
    const uint32_t B_OFF  = 2 * A_TILE_E * 2;

    // ldmatrix per-lane base addresses (byte offsets within a stage)
    const int aRow = wm * 32 + (lid & 7) + ((lid >> 3) & 1) * 8;
    const int aK   = (lid >> 4) * 8;
    const uint32_t aOff = (uint32_t)((aRow * SAPAD + aK) * 2);
    const int bRow = wn * 32 + (lid & 7) + (lid >> 4) * 8;
    const int bK   = ((lid >> 3) & 1) * 8;
    const uint32_t bOff = (uint32_t)((bRow * SAPAD + bK) * 2);

    float acc[2][4][4];
#pragma unroll
    for (int a = 0; a < 2; a++)
#pragma unroll
        for (int b = 0; b < 4; b++)
#pragma unroll
            for (int c = 0; c < 4; c++) acc[a][b][c] = 0.0f;

    // ---- fill stage 0 ----
    {
        // B via cp.async: single tile, 2 chunks of 16B per thread
#pragma unroll
        for (int j = 0; j < 2; j++) {
            const int cid = tid + j * 256;        // 0..511
            const int r   = cid >> 2;             // 0..127
            const int kc  = cid & 3;
            const uint32_t dst = smBase + B_OFF + (uint32_t)((r * SAPAD + kc * 8) * 2);
            cp_async16(dst, Wp + (size_t)r * I_DIM + kc * 8);
        }
        cp_commit();
        // A via LDG + hi/lo split + STS.128
        float4 va0 = *(const float4*)(Ap + (size_t)aLRow * strideA + aLK);
        float4 va1 = *(const float4*)(Ap + (size_t)aLRow * strideA + aLK + 4);
        uint2 h0, l0, h1, l1;
        cvt_hilo_f16(va0, h0, l0);
        cvt_hilo_f16(va1, h1, l1);
        const int off = aLRow * SAPAD + aLK;
        *(uint4*)(sm + off)            = make_uint4(h0.x, h0.y, h1.x, h1.y);
        *(uint4*)(sm + A_TILE_E + off) = make_uint4(l0.x, l0.y, l1.x, l1.y);
        cp_wait0();
    }
    __syncthreads();

    float4 ra0, ra1;

    for (int it = 0; it < NITER; it++) {
        // issue next-stage B cp.async + prefetch next A into registers
        if (it + 1 < NITER) {
            const int k0n = (it + 1) * BK;
            const uint32_t nstage = smBase + (uint32_t)((it + 1) & 1) * (STAGE_E * 2);
#pragma unroll
            for (int j = 0; j < 2; j++) {
                const int cid = tid + j * 256;
                const int r   = cid >> 2;
                const int kc  = cid & 3;
                const uint32_t dst = nstage + B_OFF + (uint32_t)((r * SAPAD + kc * 8) * 2);
                cp_async16(dst, Wp + (size_t)r * I_DIM + k0n + kc * 8);
            }
            cp_commit();
            ra0 = *(const float4*)(Ap + (size_t)aLRow * strideA + k0n + aLK);
            ra1 = *(const float4*)(Ap + (size_t)aLRow * strideA + k0n + aLK + 4);
        }

        // compute current stage via ldmatrix + mma (2 passes: xh*w, xl*w)
        {
            const uint32_t stage = smBase + (uint32_t)(it & 1) * (STAGE_E * 2);
            const uint32_t aAddr = stage + aOff;
            const uint32_t bAddr = stage + B_OFF + bOff;   // FIX: include B region base

#pragma unroll
            for (int ks = 0; ks < 2; ks++) {
                const uint32_t kd = (uint32_t)(ks * 32);   // 16 halves = 32 B
                uint32_t aH[2][4], aL[2][4], bF[4][2];
#pragma unroll
                for (int mf = 0; mf < 2; mf++) {
                    const uint32_t md = (uint32_t)(mf * 16 * SAPAD * 2);
                    ldsm_x4(aH[mf][0], aH[mf][1], aH[mf][2], aH[mf][3],
                            aAddr + AH_OFF + md + kd);
                    ldsm_x4(aL[mf][0], aL[mf][1], aL[mf][2], aL[mf][3],
                            aAddr + AL_OFF + md + kd);
                }
#pragma unroll
                for (int nfp = 0; nfp < 2; nfp++) {
                    const uint32_t nd = (uint32_t)(nfp * 16 * SAPAD * 2);
                    ldsm_x4(bF[nfp * 2][0], bF[nfp * 2][1], bF[nfp * 2 + 1][0],
                            bF[nfp * 2 + 1][1], bAddr + nd + kd);
                }
#pragma unroll
                for (int mf = 0; mf < 2; mf++)
#pragma unroll
                    for (int nf = 0; nf < 4; nf++) {
                        mma_f16(acc[mf][nf], aH[mf], bF[nf]);  // xh * w
                        mma_f16(acc[mf][nf], aL[mf], bF[nf]);  // xl * w
                    }
            }
        }

        // store next-stage A, then wait for B cp.async and sync
        if (it + 1 < NITER) {
            __half* nsm = sm + (size_t)((it + 1) & 1) * STAGE_E;
            uint2 h0, l0, h1, l1;
            cvt_hilo_f16(ra0, h0, l0);
            cvt_hilo_f16(ra1, h1, l1);
            const int off = aLRow * SAPAD + aLK;
            *(uint4*)(nsm + off)            = make_uint4(h0.x, h0.y, h1.x, h1.y);
            *(uint4*)(nsm + A_TILE_E + off) = make_uint4(l0.x, l0.y, l1.x, l1.y);
            cp_wait0();
        }
        __syncthreads();
    }

    // ---------------- epilogue: bias + direct stores ----------------
    const float* bptr = bias + (size_t)grp * O_DIM + (size_t)nt * BN;
#pragma unroll
    for (int nf = 0; nf < 4; nf++) {
        const int col = wn * 32 + nf * 8 + 2 * q;
        const float b0 = bptr[col];
        const float b1 = bptr[col + 1];
#pragma unroll
        for (int mf = 0; mf < 2; mf++) {
            const int row0 = mt * BM + wm * 32 + mf * 16 + gq;
            float2 v0, v1;
            v0.x = acc[mf][nf][0] + b0;
            v0.y = acc[mf][nf][1] + b1;
            v1.x = acc[mf][nf][2] + b0;
            v1.y = acc[mf][nf][3] + b1;
            float* o0 = out + (size_t)row0 * strideC + (size_t)v * O_DIM + nt * BN + col;
            *(float2*)o0 = v0;
            *(float2*)(o0 + 8 * strideC) = v1;
        }
    }
}

extern "C" void kernel_launch(void* const* d_in, const int* in_sizes, int n_in,
                              void* d_out, int out_size) {
    const float* x    = nullptr;
    const void*  gidx = nullptr;
    const float* w    = nullptr;
    const float* b    = nullptr;
    for (int i = 0; i < n_in; i++) {
        switch (in_sizes[i]) {
            case 67108864: x    = (const float*)d_in[i]; break;
            case 1024:     gidx = d_in[i];               break;
            case 4194304:  w    = (const float*)d_in[i]; break;
            case 8192:     b    = (const float*)d_in[i]; break;
            default: break;
        }
    }
    if (!x)    x    = (const float*)d_in[0];
    if (!gidx) gidx = d_in[1];
    if (!w)    w    = (const float*)d_in[2];
    if (!b)    b    = (const float*)d_in[3];

    float* out = (float*)d_out;

    static bool attr_done = false;
    if (!attr_done) {
        cudaFuncSetAttribute(glinear_mma_kernel,
                             cudaFuncAttributeMaxDynamicSharedMemorySize, SMEM_BYTES);
        attr_done = true;
    }

    decode_gidx_kernel<<<1, V_DIM>>>((const int*)gidx);
    convert_w_kernel<<<(G_DIM * O_DIM * I_DIM / 4) / 256, 256>>>(w);
    glinear_mma_kernel<<<V_DIM * 8, 256, SMEM_BYTES>>>(x, b, out);
}

// round 14
// speedup vs baseline: 3.5896x; 1.1209x over previous
#include <cuda_runtime.h>
#include <cuda_fp16.h>
#include <stdint.h>

#define B_DIM 128
#define V_DIM 1024
#define I_DIM 512
#define O_DIM 512
#define G_DIM 16

#define BM 128
#define BN 128
#define BK 32
#define NITER (I_DIM / BK)

#define SAPAD 40                    // fp16 row stride: 80B (16B-aligned rows, conflict-free LDSM)
#define A_TILE_E (128 * SAPAD)      // 5120 halves (one A half-matrix: 128 rows x 32 k padded)
#define B_TILE_E (128 * SAPAD)      // 5120 halves
#define STAGE_E (2 * A_TILE_E + B_TILE_E)       // AH,AL,B = 15360 halves
#define SMEM_BYTES (2 * STAGE_E * 2)            // 2 stages -> 61440 B

// ---------------- static scratch: pre-converted fp16 weights ----------------
__device__ __half wh_buf[G_DIM * O_DIM * I_DIM];   // 8 MB

// ---------------- group-index decode (int32/int64 robust) ----------------
__device__ int g_decoded[V_DIM];

__global__ void decode_gidx_kernel(const int* __restrict__ gidx_i32) {
    __shared__ int is_i32;
    const int v = threadIdx.x;
    if (v == 0) is_i32 = 0;
    __syncthreads();
    {
        const int w = gidx_i32[v];
        if (v & 1) { if (w != 0) atomicOr(&is_i32, 1); }
        else       { if (w < 0 || w >= G_DIM) atomicOr(&is_i32, 1); }
    }
    __syncthreads();
    int g = is_i32 ? gidx_i32[v] : gidx_i32[2 * v];
    if (g < 0) g = 0;
    if (g >= G_DIM) g = G_DIM - 1;
    g_decoded[v] = g;
}

// ---------------- helpers ----------------
__device__ __forceinline__ uint32_t pack_h2(__half a, __half b) {
    return (uint32_t)__half_as_ushort(a) | ((uint32_t)__half_as_ushort(b) << 16);
}

// split float4 into fp16 hi + fp16 residual lo
__device__ __forceinline__ void cvt_hilo_f16(float4 v, uint2& hi, uint2& lo) {
    __half h0 = __float2half_rn(v.x);
    __half h1 = __float2half_rn(v.y);
    __half h2 = __float2half_rn(v.z);
    __half h3 = __float2half_rn(v.w);
    __half l0 = __float2half_rn(v.x - __half2float(h0));
    __half l1 = __float2half_rn(v.y - __half2float(h1));
    __half l2 = __float2half_rn(v.z - __half2float(h2));
    __half l3 = __float2half_rn(v.w - __half2float(h3));
    hi.x = pack_h2(h0, h1); hi.y = pack_h2(h2, h3);
    lo.x = pack_h2(l0, l1); lo.y = pack_h2(l2, l3);
}

// single fp16 conversion of float4
__device__ __forceinline__ uint2 cvt_f16(float4 v) {
    uint2 r;
    r.x = pack_h2(__float2half_rn(v.x), __float2half_rn(v.y));
    r.y = pack_h2(__float2half_rn(v.z), __float2half_rn(v.w));
    return r;
}

__device__ __forceinline__ void mma_f16(float* d, const uint32_t* a, const uint32_t* b) {
    asm volatile(
        "mma.sync.aligned.m16n8k16.row.col.f32.f16.f16.f32 "
        "{%0,%1,%2,%3}, {%4,%5,%6,%7}, {%8,%9}, {%0,%1,%2,%3};"
        : "+f"(d[0]), "+f"(d[1]), "+f"(d[2]), "+f"(d[3])
        : "r"(a[0]), "r"(a[1]), "r"(a[2]), "r"(a[3]), "r"(b[0]), "r"(b[1]));
}

__device__ __forceinline__ void ldsm_x4(uint32_t& r0, uint32_t& r1, uint32_t& r2,
                                        uint32_t& r3, uint32_t addr) {
    asm volatile("ldmatrix.sync.aligned.m8n8.x4.shared.b16 {%0,%1,%2,%3}, [%4];"
                 : "=r"(r0), "=r"(r1), "=r"(r2), "=r"(r3) : "r"(addr));
}

__device__ __forceinline__ void cp_async16(uint32_t smem_addr, const void* gptr) {
    asm volatile("cp.async.cg.shared.global [%0], [%1], 16;"
                 :: "r"(smem_addr), "l"(gptr) : "memory");
}
__device__ __forceinline__ void cp_commit() {
    asm volatile("cp.async.commit_group;" ::: "memory");
}
__device__ __forceinline__ void cp_wait0() {
    asm volatile("cp.async.wait_group 0;" ::: "memory");
}

// ---------------- weight fp16-convert prepass (idempotent) ------
__global__ void convert_w_kernel(const float* __restrict__ w) {
    const int i = blockIdx.x * 256 + threadIdx.x;   // indexes float4 (1M total)
    float4 v = ((const float4*)w)[i];
    ((uint2*)wh_buf)[i] = cvt_f16(v);
}

// ---------------- main kernel ----------------
__global__ void __launch_bounds__(256, 2) glinear_mma_kernel(
    const float* __restrict__ x,        // [B, V, I]
    const float* __restrict__ bias,     // [G, O]
    float* __restrict__ out)            // [B, V, O]
{
    extern __shared__ __half sm[];

    const int tid = threadIdx.x;
    const int wid = tid >> 5;
    const int lid = tid & 31;
    const int q   = lid & 3;      // 0..3
    const int gq  = lid >> 2;     // 0..7
    const int wm  = wid >> 1;     // 0..3  (M tiles of 32)
    const int wn  = wid & 1;      // 0..1  (N tiles of 64)

    const int bid = blockIdx.x;
    const int v   = bid >> 2;
    const int nt  = bid & 3;      // N block of 128
    const int grp = g_decoded[v];

    const float* Ap = x + (size_t)v * I_DIM;
    const __half* Wp = wh_buf + ((size_t)grp * O_DIM + (size_t)nt * BN) * I_DIM;
    const size_t strideA = (size_t)V_DIM * I_DIM;
    const size_t strideC = (size_t)V_DIM * O_DIM;

    // ---- A loader: 2 chunks of 8 f32 per thread (rows 0..127, kchunk 0..3) ----
    // chunk id c = tid + j*256 (0..511): row = c>>2, kc = (c&3)*8

    const uint32_t smBase = (uint32_t)__cvta_generic_to_shared(sm);

    const uint32_t AL_OFF = A_TILE_E * 2;
    const uint32_t B_OFF  = 2 * A_TILE_E * 2;

    // ldmatrix per-lane base addresses (byte offsets within a stage)
    const int aRow = wm * 32 + (lid & 7) + ((lid >> 3) & 1) * 8;
    const int aK   = (lid >> 4) * 8;
    const uint32_t aOff = (uint32_t)((aRow * SAPAD + aK) * 2);
    const int bRow = wn * 64 + (lid & 7) + (lid >> 4) * 8;
    const int bK   = ((lid >> 3) & 1) * 8;
    const uint32_t bOff = (uint32_t)((bRow * SAPAD + bK) * 2);

    float acc[2][8][4];
#pragma unroll
    for (int a = 0; a < 2; a++)
#pragma unroll
        for (int b = 0; b < 8; b++)
#pragma unroll
            for (int c = 0; c < 4; c++) acc[a][b][c] = 0.0f;

    // ---- fill stage 0 ----
    {
        // B via cp.async: 2 chunks of 16B per thread
#pragma unroll
        for (int j = 0; j < 2; j++) {
            const int cid = tid + j * 256;        // 0..511
            const int r   = cid >> 2;             // 0..127
            const int kc  = cid & 3;
            const uint32_t dst = smBase + B_OFF + (uint32_t)((r * SAPAD + kc * 8) * 2);
            cp_async16(dst, Wp + (size_t)r * I_DIM + kc * 8);
        }
        cp_commit();
        // A via LDG + hi/lo split + STS.128 (2 chunks per thread)
#pragma unroll
        for (int j = 0; j < 2; j++) {
            const int cid = tid + j * 256;
            const int r   = cid >> 2;             // 0..127
            const int kc  = (cid & 3) * 8;
            float4 va0 = *(const float4*)(Ap + (size_t)r * strideA + kc);
            float4 va1 = *(const float4*)(Ap + (size_t)r * strideA + kc + 4);
            uint2 h0, l0, h1, l1;
            cvt_hilo_f16(va0, h0, l0);
            cvt_hilo_f16(va1, h1, l1);
            const int off = r * SAPAD + kc;
            *(uint4*)(sm + off)            = make_uint4(h0.x, h0.y, h1.x, h1.y);
            *(uint4*)(sm + A_TILE_E + off) = make_uint4(l0.x, l0.y, l1.x, l1.y);
        }
        cp_wait0();
    }
    __syncthreads();

    float4 ra0[2], ra1[2];

    for (int it = 0; it < NITER; it++) {
        // issue next-stage B cp.async + prefetch next A into registers
        if (it + 1 < NITER) {
            const int k0n = (it + 1) * BK;
            const uint32_t nstage = smBase + (uint32_t)((it + 1) & 1) * (STAGE_E * 2);
#pragma unroll
            for (int j = 0; j < 2; j++) {
                const int cid = tid + j * 256;
                const int r   = cid >> 2;
                const int kc  = cid & 3;
                const uint32_t dst = nstage + B_OFF + (uint32_t)((r * SAPAD + kc * 8) * 2);
                cp_async16(dst, Wp + (size_t)r * I_DIM + k0n + kc * 8);
            }
            cp_commit();
#pragma unroll
            for (int j = 0; j < 2; j++) {
                const int cid = tid + j * 256;
                const int r   = cid >> 2;
                const int kc  = (cid & 3) * 8;
                ra0[j] = *(const float4*)(Ap + (size_t)r * strideA + k0n + kc);
                ra1[j] = *(const float4*)(Ap + (size_t)r * strideA + k0n + kc + 4);
            }
        }

        // compute current stage via ldmatrix + mma (2 passes: xh*w, xl*w)
        {
            const uint32_t stage = smBase + (uint32_t)(it & 1) * (STAGE_E * 2);
            const uint32_t aAddr = stage + aOff;
            const uint32_t bAddr = stage + B_OFF + bOff;

#pragma unroll
            for (int ks = 0; ks < 2; ks++) {
                const uint32_t kd = (uint32_t)(ks * 32);   // 16 halves = 32 B
                uint32_t aH[2][4], aL[2][4], bF[8][2];
#pragma unroll
                for (int mf = 0; mf < 2; mf++) {
                    const uint32_t md = (uint32_t)(mf * 16 * SAPAD * 2);
                    ldsm_x4(aH[mf][0], aH[mf][1], aH[mf][2], aH[mf][3],
                            aAddr + md + kd);
                    ldsm_x4(aL[mf][0], aL[mf][1], aL[mf][2], aL[mf][3],
                            aAddr + AL_OFF + md + kd);
                }
#pragma unroll
                for (int nfp = 0; nfp < 4; nfp++) {
                    const uint32_t nd = (uint32_t)(nfp * 16 * SAPAD * 2);
                    ldsm_x4(bF[nfp * 2][0], bF[nfp * 2][1], bF[nfp * 2 + 1][0],
                            bF[nfp * 2 + 1][1], bAddr + nd + kd);
                }
#pragma unroll
                for (int mf = 0; mf < 2; mf++)
#pragma unroll
                    for (int nf = 0; nf < 8; nf++) {
                        mma_f16(acc[mf][nf], aH[mf], bF[nf]);  // xh * w
                        mma_f16(acc[mf][nf], aL[mf], bF[nf]);  // xl * w
                    }
            }
        }

        // store next-stage A, then wait for B cp.async and sync
        if (it + 1 < NITER) {
            __half* nsm = sm + (size_t)((it + 1) & 1) * STAGE_E;
#pragma unroll
            for (int j = 0; j < 2; j++) {
                const int cid = tid + j * 256;
                const int r   = cid >> 2;
                const int kc  = (cid & 3) * 8;
                uint2 h0, l0, h1, l1;
                cvt_hilo_f16(ra0[j], h0, l0);
                cvt_hilo_f16(ra1[j], h1, l1);
                const int off = r * SAPAD + kc;
                *(uint4*)(nsm + off)            = make_uint4(h0.x, h0.y, h1.x, h1.y);
                *(uint4*)(nsm + A_TILE_E + off) = make_uint4(l0.x, l0.y, l1.x, l1.y);
            }
            cp_wait0();
        }
        __syncthreads();
    }

    // ---------------- epilogue: bias + direct stores ----------------
    const float* bptr = bias + (size_t)grp * O_DIM + (size_t)nt * BN;
#pragma unroll
    for (int nf = 0; nf < 8; nf++) {
        const int col = wn * 64 + nf * 8 + 2 * q;
        const float b0 = bptr[col];
        const float b1 = bptr[col + 1];
#pragma unroll
        for (int mf = 0; mf < 2; mf++) {
            const int row0 = wm * 32 + mf * 16 + gq;
            float2 v0, v1;
            v0.x = acc[mf][nf][0] + b0;
            v0.y = acc[mf][nf][1] + b1;
            v1.x = acc[mf][nf][2] + b0;
            v1.y = acc[mf][nf][3] + b1;
            float* o0 = out + (size_t)row0 * strideC + (size_t)v * O_DIM + nt * BN + col;
            *(float2*)o0 = v0;
            *(float2*)(o0 + 8 * strideC) = v1;
        }
    }
}

extern "C" void kernel_launch(void* const* d_in, const int* in_sizes, int n_in,
                              void* d_out, int out_size) {
    const float* x    = nullptr;
    const void*  gidx = nullptr;
    const float* w    = nullptr;
    const float* b    = nullptr;
    for (int i = 0; i < n_in; i++) {
        switch (in_sizes[i]) {
            case 67108864: x    = (const float*)d_in[i]; break;
            case 1024:     gidx = d_in[i];               break;
            case 4194304:  w    = (const float*)d_in[i]; break;
            case 8192:     b    = (const float*)d_in[i]; break;
            default: break;
        }
    }
    if (!x)    x    = (const float*)d_in[0];
    if (!gidx) gidx = d_in[1];
    if (!w)    w    = (const float*)d_in[2];
    if (!b)    b    = (const float*)d_in[3];

    float* out = (float*)d_out;

    static bool attr_done = false;
    if (!attr_done) {
        cudaFuncSetAttribute(glinear_mma_kernel,
                             cudaFuncAttributeMaxDynamicSharedMemorySize, SMEM_BYTES);
        attr_done = true;
    }

    decode_gidx_kernel<<<1, V_DIM>>>((const int*)gidx);
    convert_w_kernel<<<(G_DIM * O_DIM * I_DIM / 4) / 256, 256>>>(w);
    glinear_mma_kernel<<<V_DIM * 4, 256, SMEM_BYTES>>>(x, b, out);
}

// round 15
// speedup vs baseline: 4.5349x; 1.2633x over previous
#include <cuda_runtime.h>
#include <cuda_fp16.h>
#include <stdint.h>

#define B_DIM 128
#define V_DIM 1024
#define I_DIM 512
#define O_DIM 512
#define G_DIM 16

#define BM 128
#define BN 128
#define BK 32
#define NITER (I_DIM / BK)

#define SAPAD 40                    // fp16 row stride: 80B (16B-aligned rows, conflict-free LDSM)
#define A_TILE_E (128 * SAPAD)      // 5120 halves
#define B_TILE_E (128 * SAPAD)      // 5120 halves
#define STAGE_E (A_TILE_E + B_TILE_E)           // A,B = 10240 halves
#define SMEM_BYTES (2 * STAGE_E * 2)            // 2 stages -> 40960 B

// ---------------- static scratch: pre-converted fp16 weights ----------------
__device__ __half wh_buf[G_DIM * O_DIM * I_DIM];   // 8 MB

// ---------------- group-index decode (int32/int64 robust) ----------------
__device__ int g_decoded[V_DIM];

__global__ void decode_gidx_kernel(const int* __restrict__ gidx_i32) {
    __shared__ int is_i32;
    const int v = threadIdx.x;
    if (v == 0) is_i32 = 0;
    __syncthreads();
    {
        const int w = gidx_i32[v];
        if (v & 1) { if (w != 0) atomicOr(&is_i32, 1); }
        else       { if (w < 0 || w >= G_DIM) atomicOr(&is_i32, 1); }
    }
    __syncthreads();
    int g = is_i32 ? gidx_i32[v] : gidx_i32[2 * v];
    if (g < 0) g = 0;
    if (g >= G_DIM) g = G_DIM - 1;
    g_decoded[v] = g;
}

// ---------------- helpers ----------------
__device__ __forceinline__ uint32_t pack_h2(__half a, __half b) {
    return (uint32_t)__half_as_ushort(a) | ((uint32_t)__half_as_ushort(b) << 16);
}

// single fp16 conversion of float4
__device__ __forceinline__ uint2 cvt_f16(float4 v) {
    uint2 r;
    r.x = pack_h2(__float2half_rn(v.x), __float2half_rn(v.y));
    r.y = pack_h2(__float2half_rn(v.z), __float2half_rn(v.w));
    return r;
}

__device__ __forceinline__ void mma_f16(float* d, const uint32_t* a, const uint32_t* b) {
    asm volatile(
        "mma.sync.aligned.m16n8k16.row.col.f32.f16.f16.f32 "
        "{%0,%1,%2,%3}, {%4,%5,%6,%7}, {%8,%9}, {%0,%1,%2,%3};"
        : "+f"(d[0]), "+f"(d[1]), "+f"(d[2]), "+f"(d[3])
        : "r"(a[0]), "r"(a[1]), "r"(a[2]), "r"(a[3]), "r"(b[0]), "r"(b[1]));
}

__device__ __forceinline__ void ldsm_x4(uint32_t& r0, uint32_t& r1, uint32_t& r2,
                                        uint32_t& r3, uint32_t addr) {
    asm volatile("ldmatrix.sync.aligned.m8n8.x4.shared.b16 {%0,%1,%2,%3}, [%4];"
                 : "=r"(r0), "=r"(r1), "=r"(r2), "=r"(r3) : "r"(addr));
}

__device__ __forceinline__ void cp_async16(uint32_t smem_addr, const void* gptr) {
    asm volatile("cp.async.cg.shared.global [%0], [%1], 16;"
                 :: "r"(smem_addr), "l"(gptr) : "memory");
}
__device__ __forceinline__ void cp_commit() {
    asm volatile("cp.async.commit_group;" ::: "memory");
}
__device__ __forceinline__ void cp_wait0() {
    asm volatile("cp.async.wait_group 0;" ::: "memory");
}

// ---------------- weight fp16-convert prepass (idempotent) ------
__global__ void convert_w_kernel(const float* __restrict__ w) {
    const int i = blockIdx.x * 256 + threadIdx.x;   // indexes float4 (1M total)
    float4 v = ((const float4*)w)[i];
    ((uint2*)wh_buf)[i] = cvt_f16(v);
}

// ---------------- main kernel ----------------
__global__ void __launch_bounds__(256, 2) glinear_mma_kernel(
    const float* __restrict__ x,        // [B, V, I]
    const float* __restrict__ bias,     // [G, O]
    float* __restrict__ out)            // [B, V, O]
{
    extern __shared__ __half sm[];

    const int tid = threadIdx.x;
    const int wid = tid >> 5;
    const int lid = tid & 31;
    const int q   = lid & 3;      // 0..3
    const int gq  = lid >> 2;     // 0..7
    const int wm  = wid >> 1;     // 0..3  (M tiles of 32)
    const int wn  = wid & 1;      // 0..1  (N tiles of 64)

    const int bid = blockIdx.x;
    const int v   = bid >> 2;
    const int nt  = bid & 3;      // N block of 128
    const int grp = g_decoded[v];

    const float* Ap = x + (size_t)v * I_DIM;
    const __half* Wp = wh_buf + ((size_t)grp * O_DIM + (size_t)nt * BN) * I_DIM;
    const size_t strideA = (size_t)V_DIM * I_DIM;
    const size_t strideC = (size_t)V_DIM * O_DIM;

    const uint32_t smBase = (uint32_t)__cvta_generic_to_shared(sm);
    const uint32_t B_OFF  = A_TILE_E * 2;

    // ldmatrix per-lane base addresses (byte offsets within a stage)
    const int aRow = wm * 32 + (lid & 7) + ((lid >> 3) & 1) * 8;
    const int aK   = (lid >> 4) * 8;
    const uint32_t aOff = (uint32_t)((aRow * SAPAD + aK) * 2);
    const int bRow = wn * 64 + (lid & 7) + (lid >> 4) * 8;
    const int bK   = ((lid >> 3) & 1) * 8;
    const uint32_t bOff = (uint32_t)((bRow * SAPAD + bK) * 2);

    float acc[2][8][4];
#pragma unroll
    for (int a = 0; a < 2; a++)
#pragma unroll
        for (int b = 0; b < 8; b++)
#pragma unroll
            for (int c = 0; c < 4; c++) acc[a][b][c] = 0.0f;

    // ---- fill stage 0 ----
    {
        // B via cp.async: 2 chunks of 16B per thread
#pragma unroll
        for (int j = 0; j < 2; j++) {
            const int cid = tid + j * 256;        // 0..511
            const int r   = cid >> 2;             // 0..127
            const int kc  = cid & 3;
            const uint32_t dst = smBase + B_OFF + (uint32_t)((r * SAPAD + kc * 8) * 2);
            cp_async16(dst, Wp + (size_t)r * I_DIM + kc * 8);
        }
        cp_commit();
        // A via LDG + fp16 convert + STS.128 (2 chunks per thread)
#pragma unroll
        for (int j = 0; j < 2; j++) {
            const int cid = tid + j * 256;
            const int r   = cid >> 2;             // 0..127
            const int kc  = (cid & 3) * 8;
            float4 va0 = *(const float4*)(Ap + (size_t)r * strideA + kc);
            float4 va1 = *(const float4*)(Ap + (size_t)r * strideA + kc + 4);
            uint2 c0 = cvt_f16(va0);
            uint2 c1 = cvt_f16(va1);
            *(uint4*)(sm + r * SAPAD + kc) = make_uint4(c0.x, c0.y, c1.x, c1.y);
        }
        cp_wait0();
    }
    __syncthreads();

    float4 ra0[2], ra1[2];

    for (int it = 0; it < NITER; it++) {
        // issue next-stage B cp.async + prefetch next A into registers
        if (it + 1 < NITER) {
            const int k0n = (it + 1) * BK;
            const uint32_t nstage = smBase + (uint32_t)((it + 1) & 1) * (STAGE_E * 2);
#pragma unroll
            for (int j = 0; j < 2; j++) {
                const int cid = tid + j * 256;
                const int r   = cid >> 2;
                const int kc  = cid & 3;
                const uint32_t dst = nstage + B_OFF + (uint32_t)((r * SAPAD + kc * 8) * 2);
                cp_async16(dst, Wp + (size_t)r * I_DIM + k0n + kc * 8);
            }
            cp_commit();
#pragma unroll
            for (int j = 0; j < 2; j++) {
                const int cid = tid + j * 256;
                const int r   = cid >> 2;
                const int kc  = (cid & 3) * 8;
                ra0[j] = *(const float4*)(Ap + (size_t)r * strideA + k0n + kc);
                ra1[j] = *(const float4*)(Ap + (size_t)r * strideA + k0n + kc + 4);
            }
        }

        // compute current stage via ldmatrix + single-pass fp16 mma
        {
            const uint32_t stage = smBase + (uint32_t)(it & 1) * (STAGE_E * 2);
            const uint32_t aAddr = stage + aOff;
            const uint32_t bAddr = stage + B_OFF + bOff;

#pragma unroll
            for (int ks = 0; ks < 2; ks++) {
                const uint32_t kd = (uint32_t)(ks * 32);   // 16 halves = 32 B
                uint32_t aF[2][4], bF[8][2];
#pragma unroll
                for (int mf = 0; mf < 2; mf++) {
                    const uint32_t md = (uint32_t)(mf * 16 * SAPAD * 2);
                    ldsm_x4(aF[mf][0], aF[mf][1], aF[mf][2], aF[mf][3],
                            aAddr + md + kd);
                }
#pragma unroll
                for (int nfp = 0; nfp < 4; nfp++) {
                    const uint32_t nd = (uint32_t)(nfp * 16 * SAPAD * 2);
                    ldsm_x4(bF[nfp * 2][0], bF[nfp * 2][1], bF[nfp * 2 + 1][0],
                            bF[nfp * 2 + 1][1], bAddr + nd + kd);
                }
#pragma unroll
                for (int mf = 0; mf < 2; mf++)
#pragma unroll
                    for (int nf = 0; nf < 8; nf++)
                        mma_f16(acc[mf][nf], aF[mf], bF[nf]);
            }
        }

        // store next-stage A, then wait for B cp.async and sync
        if (it + 1 < NITER) {
            __half* nsm = sm + (size_t)((it + 1) & 1) * STAGE_E;
#pragma unroll
            for (int j = 0; j < 2; j++) {
                const int cid = tid + j * 256;
                const int r   = cid >> 2;
                const int kc  = (cid & 3) * 8;
                uint2 c0 = cvt_f16(ra0[j]);
                uint2 c1 = cvt_f16(ra1[j]);
                *(uint4*)(nsm + r * SAPAD + kc) = make_uint4(c0.x, c0.y, c1.x, c1.y);
            }
            cp_wait0();
        }
        __syncthreads();
    }

    // ---------------- epilogue: bias + direct stores ----------------
    const float* bptr = bias + (size_t)grp * O_DIM + (size_t)nt * BN;
#pragma unroll
    for (int nf = 0; nf < 8; nf++) {
        const int col = wn * 64 + nf * 8 + 2 * q;
        const float b0 = bptr[col];
        const float b1 = bptr[col + 1];
#pragma unroll
        for (int mf = 0; mf < 2; mf++) {
            const int row0 = wm * 32 + mf * 16 + gq;
            float2 v0, v1;
            v0.x = acc[mf][nf][0] + b0;
            v0.y = acc[mf][nf][1] + b1;
            v1.x = acc[mf][nf][2] + b0;
            v1.y = acc[mf][nf][3] + b1;
            float* o0 = out + (size_t)row0 * strideC + (size_t)v * O_DIM + nt * BN + col;
            *(float2*)o0 = v0;
            *(float2*)(o0 + 8 * strideC) = v1;
        }
    }
}

extern "C" void kernel_launch(void* const* d_in, const int* in_sizes, int n_in,
                              void* d_out, int out_size) {
    const float* x    = nullptr;
    const void*  gidx = nullptr;
    const float* w    = nullptr;
    const float* b    = nullptr;
    for (int i = 0; i < n_in; i++) {
        switch (in_sizes[i]) {
            case 67108864: x    = (const float*)d_in[i]; break;
            case 1024:     gidx = d_in[i];               break;
            case 4194304:  w    = (const float*)d_in[i]; break;
            case 8192:     b    = (const float*)d_in[i]; break;
            default: break;
        }
    }
    if (!x)    x    = (const float*)d_in[0];
    if (!gidx) gidx = d_in[1];
    if (!w)    w    = (const float*)d_in[2];
    if (!b)    b    = (const float*)d_in[3];

    float* out = (float*)d_out;

    static bool attr_done = false;
    if (!attr_done) {
        cudaFuncSetAttribute(glinear_mma_kernel,
                             cudaFuncAttributeMaxDynamicSharedMemorySize, SMEM_BYTES);
        attr_done = true;
    }

    decode_gidx_kernel<<<1, V_DIM>>>((const int*)gidx);
    convert_w_kernel<<<(G_DIM * O_DIM * I_DIM / 4) / 256, 256>>>(w);
    glinear_mma_kernel<<<V_DIM * 4, 256, SMEM_BYTES>>>(x, b, out);
}

// round 16
// speedup vs baseline: 5.2608x; 1.1601x over previous
#include <cuda_runtime.h>
#include <cuda_fp16.h>
#include <stdint.h>

#define B_DIM 128
#define V_DIM 1024
#define I_DIM 512
#define O_DIM 512
#define G_DIM 16

#define BM 128
#define BN 128
#define BK 64
#define NITER (I_DIM / BK)

#define SAPAD 72                    // fp16 row stride: 144B (+4 banks/row -> conflict-free LDSM, 16B aligned)
#define A_TILE_E (128 * SAPAD)      // 9216 halves
#define B_TILE_E (128 * SAPAD)      // 9216 halves
#define STAGE_E (A_TILE_E + B_TILE_E)           // 18432 halves
#define SMEM_BYTES (2 * STAGE_E * 2)            // 2 stages -> 73728 B

// ---------------- static scratch: pre-converted fp16 weights ----------------
__device__ __half wh_buf[G_DIM * O_DIM * I_DIM];   // 8 MB

// ---------------- group-index decode (int32/int64 robust) ----------------
__device__ int g_decoded[V_DIM];

__global__ void decode_gidx_kernel(const int* __restrict__ gidx_i32) {
    __shared__ int is_i32;
    const int v = threadIdx.x;
    if (v == 0) is_i32 = 0;
    __syncthreads();
    {
        const int w = gidx_i32[v];
        if (v & 1) { if (w != 0) atomicOr(&is_i32, 1); }
        else       { if (w < 0 || w >= G_DIM) atomicOr(&is_i32, 1); }
    }
    __syncthreads();
    int g = is_i32 ? gidx_i32[v] : gidx_i32[2 * v];
    if (g < 0) g = 0;
    if (g >= G_DIM) g = G_DIM - 1;
    g_decoded[v] = g;
}

// ---------------- helpers ----------------
__device__ __forceinline__ uint32_t pack_h2(__half a, __half b) {
    return (uint32_t)__half_as_ushort(a) | ((uint32_t)__half_as_ushort(b) << 16);
}

// single fp16 conversion of float4
__device__ __forceinline__ uint2 cvt_f16(float4 v) {
    uint2 r;
    r.x = pack_h2(__float2half_rn(v.x), __float2half_rn(v.y));
    r.y = pack_h2(__float2half_rn(v.z), __float2half_rn(v.w));
    return r;
}

__device__ __forceinline__ void mma_f16(float* d, const uint32_t* a, const uint32_t* b) {
    asm volatile(
        "mma.sync.aligned.m16n8k16.row.col.f32.f16.f16.f32 "
        "{%0,%1,%2,%3}, {%4,%5,%6,%7}, {%8,%9}, {%0,%1,%2,%3};"
        : "+f"(d[0]), "+f"(d[1]), "+f"(d[2]), "+f"(d[3])
        : "r"(a[0]), "r"(a[1]), "r"(a[2]), "r"(a[3]), "r"(b[0]), "r"(b[1]));
}

__device__ __forceinline__ void ldsm_x4(uint32_t& r0, uint32_t& r1, uint32_t& r2,
                                        uint32_t& r3, uint32_t addr) {
    asm volatile("ldmatrix.sync.aligned.m8n8.x4.shared.b16 {%0,%1,%2,%3}, [%4];"
                 : "=r"(r0), "=r"(r1), "=r"(r2), "=r"(r3) : "r"(addr));
}

__device__ __forceinline__ void cp_async16(uint32_t smem_addr, const void* gptr) {
    asm volatile("cp.async.cg.shared.global [%0], [%1], 16;"
                 :: "r"(smem_addr), "l"(gptr) : "memory");
}
__device__ __forceinline__ void cp_commit() {
    asm volatile("cp.async.commit_group;" ::: "memory");
}
__device__ __forceinline__ void cp_wait0() {
    asm volatile("cp.async.wait_group 0;" ::: "memory");
}

// ---------------- weight fp16-convert prepass (idempotent) ------
__global__ void convert_w_kernel(const float* __restrict__ w) {
    const int i = blockIdx.x * 256 + threadIdx.x;   // indexes float4 (1M total)
    float4 v = ((const float4*)w)[i];
    ((uint2*)wh_buf)[i] = cvt_f16(v);
}

// ---------------- main kernel ----------------
__global__ void __launch_bounds__(256, 2) glinear_mma_kernel(
    const float* __restrict__ x,        // [B, V, I]
    const float* __restrict__ bias,     // [G, O]
    float* __restrict__ out)            // [B, V, O]
{
    extern __shared__ __half sm[];

    const int tid = threadIdx.x;
    const int wid = tid >> 5;
    const int lid = tid & 31;
    const int q   = lid & 3;      // 0..3
    const int gq  = lid >> 2;     // 0..7
    const int wm  = wid >> 1;     // 0..3  (M tiles of 32)
    const int wn  = wid & 1;      // 0..1  (N tiles of 64)

    const int bid = blockIdx.x;
    const int v   = bid >> 2;
    const int nt  = bid & 3;      // N block of 128
    const int grp = g_decoded[v];

    const float* Ap = x + (size_t)v * I_DIM;
    const __half* Wp = wh_buf + ((size_t)grp * O_DIM + (size_t)nt * BN) * I_DIM;
    const size_t strideA = (size_t)V_DIM * I_DIM;
    const size_t strideC = (size_t)V_DIM * O_DIM;

    const uint32_t smBase = (uint32_t)__cvta_generic_to_shared(sm);
    const uint32_t B_OFF  = A_TILE_E * 2;

    // loader coords (4 chunks per thread, cid = tid + j*256, 0..1023)
    //   r = cid>>3 (0..127), kc = cid&7 (0..7): 8-half (16 B) chunks
    // ldmatrix per-lane base addresses (byte offsets within a stage)
    const int aRow = wm * 32 + (lid & 7) + ((lid >> 3) & 1) * 8;
    const int aK   = (lid >> 4) * 8;
    const uint32_t aOff = (uint32_t)((aRow * SAPAD + aK) * 2);
    const int bRow = wn * 64 + (lid & 7) + (lid >> 4) * 8;
    const int bK   = ((lid >> 3) & 1) * 8;
    const uint32_t bOff = (uint32_t)((bRow * SAPAD + bK) * 2);

    float acc[2][8][4];
#pragma unroll
    for (int a = 0; a < 2; a++)
#pragma unroll
        for (int b = 0; b < 8; b++)
#pragma unroll
            for (int c = 0; c < 4; c++) acc[a][b][c] = 0.0f;

    // ---- fill stage 0 ----
    {
#pragma unroll
        for (int j = 0; j < 4; j++) {
            const int cid = tid + j * 256;        // 0..1023
            const int r   = cid >> 3;             // 0..127
            const int kc  = cid & 7;              // 0..7
            const uint32_t dst = smBase + B_OFF + (uint32_t)((r * SAPAD + kc * 8) * 2);
            cp_async16(dst, Wp + (size_t)r * I_DIM + kc * 8);
        }
        cp_commit();
#pragma unroll
        for (int j = 0; j < 4; j++) {
            const int cid = tid + j * 256;
            const int r   = cid >> 3;             // 0..127
            const int kc  = (cid & 7) * 8;        // 0..56
            float4 va0 = *(const float4*)(Ap + (size_t)r * strideA + kc);
            float4 va1 = *(const float4*)(Ap + (size_t)r * strideA + kc + 4);
            uint2 c0 = cvt_f16(va0);
            uint2 c1 = cvt_f16(va1);
            *(uint4*)(sm + r * SAPAD + kc) = make_uint4(c0.x, c0.y, c1.x, c1.y);
        }
        cp_wait0();
    }
    __syncthreads();

    uint4 pa[4];   // prefetched A, already converted to fp16

    for (int it = 0; it < NITER; it++) {
        // issue next-stage B cp.async + prefetch-and-convert next A into registers
        if (it + 1 < NITER) {
            const int k0n = (it + 1) * BK;
            const uint32_t nstage = smBase + (uint32_t)((it + 1) & 1) * (STAGE_E * 2);
#pragma unroll
            for (int j = 0; j < 4; j++) {
                const int cid = tid + j * 256;
                const int r   = cid >> 3;
                const int kc  = cid & 7;
                const uint32_t dst = nstage + B_OFF + (uint32_t)((r * SAPAD + kc * 8) * 2);
                cp_async16(dst, Wp + (size_t)r * I_DIM + k0n + kc * 8);
            }
            cp_commit();
#pragma unroll
            for (int j = 0; j < 4; j++) {
                const int cid = tid + j * 256;
                const int r   = cid >> 3;
                const int kc  = (cid & 7) * 8;
                float4 va0 = *(const float4*)(Ap + (size_t)r * strideA + k0n + kc);
                float4 va1 = *(const float4*)(Ap + (size_t)r * strideA + k0n + kc + 4);
                uint2 c0 = cvt_f16(va0);
                uint2 c1 = cvt_f16(va1);
                pa[j] = make_uint4(c0.x, c0.y, c1.x, c1.y);
            }
        }

        // compute current stage via ldmatrix + single-pass fp16 mma (4 k16 steps)
        {
            const uint32_t stage = smBase + (uint32_t)(it & 1) * (STAGE_E * 2);
            const uint32_t aAddr = stage + aOff;
            const uint32_t bAddr = stage + B_OFF + bOff;

#pragma unroll
            for (int ks = 0; ks < 4; ks++) {
                const uint32_t kd = (uint32_t)(ks * 32);   // 16 halves = 32 B
                uint32_t aF[2][4], bF[8][2];
#pragma unroll
                for (int mf = 0; mf < 2; mf++) {
                    const uint32_t md = (uint32_t)(mf * 16 * SAPAD * 2);
                    ldsm_x4(aF[mf][0], aF[mf][1], aF[mf][2], aF[mf][3],
                            aAddr + md + kd);
                }
#pragma unroll
                for (int nfp = 0; nfp < 4; nfp++) {
                    const uint32_t nd = (uint32_t)(nfp * 16 * SAPAD * 2);
                    ldsm_x4(bF[nfp * 2][0], bF[nfp * 2][1], bF[nfp * 2 + 1][0],
                            bF[nfp * 2 + 1][1], bAddr + nd + kd);
                }
#pragma unroll
                for (int mf = 0; mf < 2; mf++)
#pragma unroll
                    for (int nf = 0; nf < 8; nf++)
                        mma_f16(acc[mf][nf], aF[mf], bF[nf]);
            }
        }

        // store next-stage A, then wait for B cp.async and sync
        if (it + 1 < NITER) {
            __half* nsm = sm + (size_t)((it + 1) & 1) * STAGE_E;
#pragma unroll
            for (int j = 0; j < 4; j++) {
                const int cid = tid + j * 256;
                const int r   = cid >> 3;
                const int kc  = (cid & 7) * 8;
                *(uint4*)(nsm + r * SAPAD + kc) = pa[j];
            }
            cp_wait0();
        }
        __syncthreads();
    }

    // ---------------- epilogue: bias + direct stores ----------------
    const float* bptr = bias + (size_t)grp * O_DIM + (size_t)nt * BN;
#pragma unroll
    for (int nf = 0; nf < 8; nf++) {
        const int col = wn * 64 + nf * 8 + 2 * q;
        const float b0 = bptr[col];
        const float b1 = bptr[col + 1];
#pragma unroll
        for (int mf = 0; mf < 2; mf++) {
            const int row0 = wm * 32 + mf * 16 + gq;
            float2 v0, v1;
            v0.x = acc[mf][nf][0] + b0;
            v0.y = acc[mf][nf][1] + b1;
            v1.x = acc[mf][nf][2] + b0;
            v1.y = acc[mf][nf][3] + b1;
            float* o0 = out + (size_t)row0 * strideC + (size_t)v * O_DIM + nt * BN + col;
            *(float2*)o0 = v0;
            *(float2*)(o0 + 8 * strideC) = v1;
        }
    }
}

extern "C" void kernel_launch(void* const* d_in, const int* in_sizes, int n_in,
                              void* d_out, int out_size) {
    const float* x    = nullptr;
    const void*  gidx = nullptr;
    const float* w    = nullptr;
    const float* b    = nullptr;
    for (int i = 0; i < n_in; i++) {
        switch (in_sizes[i]) {
            case 67108864: x    = (const float*)d_in[i]; break;
            case 1024:     gidx = d_in[i];               break;
            case 4194304:  w    = (const float*)d_in[i]; break;
            case 8192:     b    = (const float*)d_in[i]; break;
            default: break;
        }
    }
    if (!x)    x    = (const float*)d_in[0];
    if (!gidx) gidx = d_in[1];
    if (!w)    w    = (const float*)d_in[2];
    if (!b)    b    = (const float*)d_in[3];

    float* out = (float*)d_out;

    static bool attr_done = false;
    if (!attr_done) {
        cudaFuncSetAttribute(glinear_mma_kernel,
                             cudaFuncAttributeMaxDynamicSharedMemorySize, SMEM_BYTES);
        attr_done = true;
    }

    decode_gidx_kernel<<<1, V_DIM>>>((const int*)gidx);
    convert_w_kernel<<<(G_DIM * O_DIM * I_DIM / 4) / 256, 256>>>(w);
    glinear_mma_kernel<<<V_DIM * 4, 256, SMEM_BYTES>>>(x, b, out);
}